// round 9
// baseline (speedup 1.0000x reference)
#include <cuda_runtime.h>
#include <cstdint>

// ---------------------------------------------------------------------------
// StressGCN: 4-layer GCN, N=100000 nodes, E=1.6M edges, IN_C=128, HID=256.
// h = relu(LN(agg(h@W)*dis + b)) x4, bracketed by encoder / lin1+relu / lin2.
// agg[c] = sum_{(r,c) in edges} (hw[r]*dis[r]) + hw[c]*dis[c]  (self loop)
// ---------------------------------------------------------------------------

#define NNODES   100000
#define IN_C     128
#define HID      256
#define NLAYERS  4
#define LN_EPS   1e-5f

// Scratch (device globals: allocation is forbidden)
__device__ float g_h  [(size_t)NNODES * HID];      // current features
__device__ float g_hw [(size_t)NNODES * HID];      // scaled h@W (gather source)
__device__ float g_agg[(size_t)NNODES * HID];      // aggregation target
__device__ float g_h1 [(size_t)NNODES * (HID/2)];  // lin1 output
__device__ float g_dis[NNODES];
__device__ int   g_deg[NNODES];
__device__ int   g_is32;                           // 1 if edge_index is int32

// ---------------------------------------------------------------------------
// Edge-index dtype probe: under an int64 read, genuine int64 indices are all
// in [0, N); int32 data read as int64 packs two lanes -> values >= 2^32 (or
// otherwise out of range) almost surely within the probe window.
// ---------------------------------------------------------------------------
__global__ void k_detect(const long long* __restrict__ ei, int nsamp, int N) {
    __shared__ int bad;
    if (threadIdx.x == 0) bad = 0;
    __syncthreads();
    for (int i = threadIdx.x; i < nsamp; i += blockDim.x) {
        long long v = ei[i];
        if (v < 0 || v >= (long long)N) bad = 1;
    }
    __syncthreads();
    if (threadIdx.x == 0) g_is32 = bad;
}

__device__ __forceinline__ int edge_at(const void* ei, size_t pos, int is32) {
    return is32 ? ((const int*)ei)[pos]
                : (int)(((const long long*)ei)[pos]);
}

// ---------------------------------------------------------------------------
// Degree / normalization
// ---------------------------------------------------------------------------
__global__ void k_deg_init(int n) {
    int i = blockIdx.x * blockDim.x + threadIdx.x;
    if (i < n) g_deg[i] = 1;  // self loop
}

__global__ void k_deg_count(const void* __restrict__ ei, int E, int N) {
    int e = blockIdx.x * blockDim.x + threadIdx.x;
    if (e >= E) return;
    int is32 = g_is32;
    int c = edge_at(ei, (size_t)E + e, is32);   // target
    if ((unsigned)c < (unsigned)N)
        atomicAdd(&g_deg[c], 1);
}

__global__ void k_dis(int n) {
    int i = blockIdx.x * blockDim.x + threadIdx.x;
    if (i < n) g_dis[i] = rsqrtf((float)g_deg[i]);
}

// ---------------------------------------------------------------------------
// SGEMM: C[M,Nc] = A[M,K] @ B[K,Nc], tiled 128x128x16, 256 threads, 8x8/thread
// mode 0: g_h   = C + bias               (encoder)
// mode 1: g_hw = g_agg = C * dis[m]      (conv: pre-scale + self-loop init)
// mode 2: g_h1  = relu(C + bias)         (lin1)
// Aext == nullptr -> A = g_h
// ---------------------------------------------------------------------------
#define BM 128
#define BN 128
#define BKK 16

__global__ void __launch_bounds__(256)
k_gemm(const float* __restrict__ Aext, const float* __restrict__ B,
       const float* __restrict__ bias, int M, int K, int Nc, int mode) {
    const float* __restrict__ A = Aext ? Aext : g_h;

    __shared__ float As[BKK][BM + 4];
    __shared__ float Bs[BKK][BN + 4];

    const int m0 = blockIdx.x * BM;
    const int n0 = blockIdx.y * BN;
    const int tid = threadIdx.x;
    const int tr = tid >> 4;    // 0..15
    const int tc = tid & 15;    // 0..15

    float acc[8][8];
#pragma unroll
    for (int i = 0; i < 8; i++)
#pragma unroll
        for (int j = 0; j < 8; j++) acc[i][j] = 0.f;

    for (int k0 = 0; k0 < K; k0 += BKK) {
        // A tile: 128x16 = 512 float4, 2 per thread, stored transposed
#pragma unroll
        for (int l = 0; l < 2; l++) {
            int f = tid * 2 + l;
            int row = f >> 2;
            int c4 = (f & 3) * 4;
            float4 v = make_float4(0.f, 0.f, 0.f, 0.f);
            int m = m0 + row;
            if (m < M) v = *(const float4*)(A + (size_t)m * K + k0 + c4);
            As[c4 + 0][row] = v.x;
            As[c4 + 1][row] = v.y;
            As[c4 + 2][row] = v.z;
            As[c4 + 3][row] = v.w;
        }
        // B tile: 16x128 = 512 float4, 2 per thread
#pragma unroll
        for (int l = 0; l < 2; l++) {
            int f = tid * 2 + l;
            int row = f >> 5;
            int c4 = (f & 31) * 4;
            float4 v = *(const float4*)(B + (size_t)(k0 + row) * Nc + n0 + c4);
            *(float4*)&Bs[row][c4] = v;
        }
        __syncthreads();

#pragma unroll
        for (int k = 0; k < BKK; k++) {
            float ra[8], rb[8];
            *(float4*)(ra)     = *(const float4*)&As[k][tr * 8];
            *(float4*)(ra + 4) = *(const float4*)&As[k][tr * 8 + 4];
            *(float4*)(rb)     = *(const float4*)&Bs[k][tc * 8];
            *(float4*)(rb + 4) = *(const float4*)&Bs[k][tc * 8 + 4];
#pragma unroll
            for (int i = 0; i < 8; i++)
#pragma unroll
                for (int j = 0; j < 8; j++)
                    acc[i][j] += ra[i] * rb[j];
        }
        __syncthreads();
    }

    // Epilogue
    const int nbase = n0 + tc * 8;
    float bb[8];
    if (mode != 1) {
#pragma unroll
        for (int j = 0; j < 8; j++) bb[j] = bias[nbase + j];
    }

#pragma unroll
    for (int i = 0; i < 8; i++) {
        int m = m0 + tr * 8 + i;
        if (m >= M) break;
        size_t off = (size_t)m * Nc + nbase;
        if (mode == 0) {
            float4 v0, v1;
            v0.x = acc[i][0] + bb[0]; v0.y = acc[i][1] + bb[1];
            v0.z = acc[i][2] + bb[2]; v0.w = acc[i][3] + bb[3];
            v1.x = acc[i][4] + bb[4]; v1.y = acc[i][5] + bb[5];
            v1.z = acc[i][6] + bb[6]; v1.w = acc[i][7] + bb[7];
            *(float4*)(g_h + off) = v0;
            *(float4*)(g_h + off + 4) = v1;
        } else if (mode == 1) {
            float d = g_dis[m];
            float4 v0, v1;
            v0.x = acc[i][0] * d; v0.y = acc[i][1] * d;
            v0.z = acc[i][2] * d; v0.w = acc[i][3] * d;
            v1.x = acc[i][4] * d; v1.y = acc[i][5] * d;
            v1.z = acc[i][6] * d; v1.w = acc[i][7] * d;
            *(float4*)(g_hw + off) = v0;
            *(float4*)(g_hw + off + 4) = v1;
            *(float4*)(g_agg + off) = v0;      // self-loop init
            *(float4*)(g_agg + off + 4) = v1;
        } else {
            float4 v0, v1;
            v0.x = fmaxf(acc[i][0] + bb[0], 0.f); v0.y = fmaxf(acc[i][1] + bb[1], 0.f);
            v0.z = fmaxf(acc[i][2] + bb[2], 0.f); v0.w = fmaxf(acc[i][3] + bb[3], 0.f);
            v1.x = fmaxf(acc[i][4] + bb[4], 0.f); v1.y = fmaxf(acc[i][5] + bb[5], 0.f);
            v1.z = fmaxf(acc[i][6] + bb[6], 0.f); v1.w = fmaxf(acc[i][7] + bb[7], 0.f);
            *(float4*)(g_h1 + off) = v0;
            *(float4*)(g_h1 + off + 4) = v1;
        }
    }
}

// ---------------------------------------------------------------------------
// Edge scatter: warp per edge. Gather one 1KB row, vector-atomic into target.
// atomicAdd(float4*,float4): sm_90+ intrinsic -> vector RED, no return trip.
// ---------------------------------------------------------------------------
__global__ void __launch_bounds__(256)
k_scatter(const void* __restrict__ ei, int E, int N) {
    int warp = (blockIdx.x * blockDim.x + threadIdx.x) >> 5;
    if (warp >= E) return;
    int lane = threadIdx.x & 31;
    int is32 = g_is32;

    int r = edge_at(ei, warp, is32);
    int c = edge_at(ei, (size_t)E + warp, is32);
    if ((unsigned)r >= (unsigned)N || (unsigned)c >= (unsigned)N) return;

    const float4* __restrict__ src = (const float4*)(g_hw + (size_t)r * HID);
    float4*                    dst = (float4*)(g_agg + (size_t)c * HID);

    float4 v0 = __ldg(src + lane);
    float4 v1 = __ldg(src + lane + 32);
    atomicAdd(dst + lane, v0);
    atomicAdd(dst + lane + 32, v1);
}

// ---------------------------------------------------------------------------
// Finish conv layer: h = relu(LN(agg*dis + conv_b) * g + b), warp per node
// ---------------------------------------------------------------------------
__global__ void __launch_bounds__(256)
k_finish(const float* __restrict__ cb, const float* __restrict__ lg,
         const float* __restrict__ lb, int n) {
    int node = (blockIdx.x * blockDim.x + threadIdx.x) >> 5;
    if (node >= n) return;
    int lane = threadIdx.x & 31;
    size_t base = (size_t)node * HID;

    float d = g_dis[node];
    float4 a0 = *(const float4*)(g_agg + base + lane * 4);
    float4 a1 = *(const float4*)(g_agg + base + lane * 4 + 128);
    float4 c0 = ((const float4*)cb)[lane];
    float4 c1 = ((const float4*)cb)[lane + 32];

    float v[8];
    v[0] = a0.x * d + c0.x; v[1] = a0.y * d + c0.y;
    v[2] = a0.z * d + c0.z; v[3] = a0.w * d + c0.w;
    v[4] = a1.x * d + c1.x; v[5] = a1.y * d + c1.y;
    v[6] = a1.z * d + c1.z; v[7] = a1.w * d + c1.w;

    float s = 0.f, sq = 0.f;
#pragma unroll
    for (int i = 0; i < 8; i++) { s += v[i]; sq += v[i] * v[i]; }
#pragma unroll
    for (int o = 16; o > 0; o >>= 1) {
        s  += __shfl_xor_sync(0xffffffffu, s, o);
        sq += __shfl_xor_sync(0xffffffffu, sq, o);
    }
    float mu = s * (1.f / HID);
    float var = sq * (1.f / HID) - mu * mu;
    float rs = rsqrtf(var + LN_EPS);

    float4 g0 = ((const float4*)lg)[lane];
    float4 g1 = ((const float4*)lg)[lane + 32];
    float4 b0 = ((const float4*)lb)[lane];
    float4 b1 = ((const float4*)lb)[lane + 32];

    float4 o0, o1;
    o0.x = fmaxf((v[0] - mu) * rs * g0.x + b0.x, 0.f);
    o0.y = fmaxf((v[1] - mu) * rs * g0.y + b0.y, 0.f);
    o0.z = fmaxf((v[2] - mu) * rs * g0.z + b0.z, 0.f);
    o0.w = fmaxf((v[3] - mu) * rs * g0.w + b0.w, 0.f);
    o1.x = fmaxf((v[4] - mu) * rs * g1.x + b1.x, 0.f);
    o1.y = fmaxf((v[5] - mu) * rs * g1.y + b1.y, 0.f);
    o1.z = fmaxf((v[6] - mu) * rs * g1.z + b1.z, 0.f);
    o1.w = fmaxf((v[7] - mu) * rs * g1.w + b1.w, 0.f);

    *(float4*)(g_h + base + lane * 4) = o0;
    *(float4*)(g_h + base + lane * 4 + 128) = o1;
}

// ---------------------------------------------------------------------------
// lin2: out[n] = h1[n,:] . w + b, warp per node (128-dot)
// ---------------------------------------------------------------------------
__global__ void __launch_bounds__(256)
k_lin2(const float* __restrict__ w, const float* __restrict__ b,
       float* __restrict__ out, int n) {
    int node = (blockIdx.x * blockDim.x + threadIdx.x) >> 5;
    if (node >= n) return;
    int lane = threadIdx.x & 31;

    float4 h = *(const float4*)(g_h1 + (size_t)node * (HID / 2) + lane * 4);
    float4 wv = ((const float4*)w)[lane];
    float s = h.x * wv.x + h.y * wv.y + h.z * wv.z + h.w * wv.w;
#pragma unroll
    for (int o = 16; o > 0; o >>= 1)
        s += __shfl_xor_sync(0xffffffffu, s, o);
    if (lane == 0) out[node] = s + b[0];
}

// ---------------------------------------------------------------------------
// Launch
// ---------------------------------------------------------------------------
extern "C" void kernel_launch(void* const* d_in, const int* in_sizes, int n_in,
                              void* d_out, int out_size) {
    const float* x      = (const float*)d_in[0];
    const void*  ei     = d_in[1];                 // int32 or int64 — probed
    const float* enc_w  = (const float*)d_in[2];
    const float* enc_b  = (const float*)d_in[3];
    const float* conv_w = (const float*)d_in[4];
    const float* conv_b = (const float*)d_in[5];
    const float* ln_g   = (const float*)d_in[6];
    const float* ln_b   = (const float*)d_in[7];
    const float* lin1_w = (const float*)d_in[8];
    const float* lin1_b = (const float*)d_in[9];
    const float* lin2_w = (const float*)d_in[10];
    const float* lin2_b = (const float*)d_in[11];
    float* out = (float*)d_out;

    const int N = in_sizes[0] / IN_C;    // 100000
    const int E = in_sizes[1] / 2;       // 1600000

    // Probe edge_index dtype (deterministic; depends only on input content).
    // nsamp int64 reads = 2*nsamp int32 slots, safely within 2*E elements.
    int nsamp = (E >= 1024) ? 1024 : (E > 0 ? E : 1);
    k_detect<<<1, 256>>>((const long long*)ei, nsamp, N);

    // Degree + normalization (recomputed every call: deterministic work)
    k_deg_init<<<(N + 255) / 256, 256>>>(N);
    k_deg_count<<<(E + 255) / 256, 256>>>(ei, E, N);
    k_dis<<<(N + 255) / 256, 256>>>(N);

    dim3 g_enc((N + BM - 1) / BM, HID / BN);
    dim3 g_conv((N + BM - 1) / BM, HID / BN);
    dim3 g_lin1((N + BM - 1) / BM, (HID / 2) / BN);

    // Encoder: g_h = x @ enc_w + enc_b
    k_gemm<<<g_enc, 256>>>(x, enc_w, enc_b, N, IN_C, HID, 0);

    const int scatter_blocks = (int)(((size_t)E * 32 + 255) / 256);
    const int node_warp_blocks = (N * 32 + 255) / 256;

    for (int i = 0; i < NLAYERS; i++) {
        // hw = (g_h @ W_i) * dis  ;  agg initialized with self-loop term
        k_gemm<<<g_conv, 256>>>(nullptr, conv_w + (size_t)i * HID * HID,
                                nullptr, N, HID, HID, 1);
        // agg[col] += hw[row]
        k_scatter<<<scatter_blocks, 256>>>(ei, E, N);
        // h = relu(LN(agg*dis + b))
        k_finish<<<node_warp_blocks, 256>>>(conv_b + (size_t)i * HID,
                                            ln_g + (size_t)i * HID,
                                            ln_b + (size_t)i * HID, N);
    }

    // lin1 (+relu), then lin2
    k_gemm<<<g_lin1, 256>>>(nullptr, lin1_w, lin1_b, N, HID, HID / 2, 2);
    k_lin2<<<node_warp_blocks, 256>>>(lin2_w, lin2_b, out, N);
}

// round 10
// speedup vs baseline: 1.0002x; 1.0002x over previous
#include <cuda_runtime.h>
#include <cstdint>

// ---------------------------------------------------------------------------
// StressGCN: 4-layer GCN, N=100000 nodes, E=1.6M edges, IN_C=128, HID=256.
// h = relu(LN(agg(h@W)*dis + b)) x4, bracketed by encoder / lin1+relu / lin2.
// agg[c] = sum_{(r,c) in edges} (hw[r]*dis[r]) + hw[c]*dis[c]  (self loop)
// ---------------------------------------------------------------------------

#define NNODES   100000
#define IN_C     128
#define HID      256
#define NLAYERS  4
#define LN_EPS   1e-5f

// Scratch (device globals: allocation is forbidden)
__device__ float g_h  [(size_t)NNODES * HID];      // current features
__device__ float g_hw [(size_t)NNODES * HID];      // scaled h@W (gather source)
__device__ float g_agg[(size_t)NNODES * HID];      // aggregation target
__device__ float g_h1 [(size_t)NNODES * (HID/2)];  // lin1 output
__device__ float g_dis[NNODES];
__device__ int   g_deg[NNODES];
__device__ int   g_is32;                           // 1 if edge_index is int32

// ---------------------------------------------------------------------------
// Edge-index dtype probe: under an int64 read, genuine int64 indices are all
// in [0, N); int32 data read as int64 packs two lanes -> values >= 2^32 (or
// otherwise out of range) almost surely within the probe window.
// ---------------------------------------------------------------------------
__global__ void k_detect(const long long* __restrict__ ei, int nsamp, int N) {
    __shared__ int bad;
    if (threadIdx.x == 0) bad = 0;
    __syncthreads();
    for (int i = threadIdx.x; i < nsamp; i += blockDim.x) {
        long long v = ei[i];
        if (v < 0 || v >= (long long)N) bad = 1;
    }
    __syncthreads();
    if (threadIdx.x == 0) g_is32 = bad;
}

__device__ __forceinline__ int edge_at(const void* ei, size_t pos, int is32) {
    return is32 ? ((const int*)ei)[pos]
                : (int)(((const long long*)ei)[pos]);
}

// ---------------------------------------------------------------------------
// Degree / normalization
// ---------------------------------------------------------------------------
__global__ void k_deg_init(int n) {
    int i = blockIdx.x * blockDim.x + threadIdx.x;
    if (i < n) g_deg[i] = 1;  // self loop
}

__global__ void k_deg_count(const void* __restrict__ ei, int E, int N) {
    int e = blockIdx.x * blockDim.x + threadIdx.x;
    if (e >= E) return;
    int is32 = g_is32;
    int c = edge_at(ei, (size_t)E + e, is32);   // target
    if ((unsigned)c < (unsigned)N)
        atomicAdd(&g_deg[c], 1);
}

__global__ void k_dis(int n) {
    int i = blockIdx.x * blockDim.x + threadIdx.x;
    if (i < n) g_dis[i] = rsqrtf((float)g_deg[i]);
}

// ---------------------------------------------------------------------------
// SGEMM: C[M,Nc] = A[M,K] @ B[K,Nc], tiled 128x128x16, 256 threads, 8x8/thread
// mode 0: g_h   = C + bias               (encoder)
// mode 1: g_hw = g_agg = C * dis[m]      (conv: pre-scale + self-loop init)
// mode 2: g_h1  = relu(C + bias)         (lin1)
// Aext == nullptr -> A = g_h
// ---------------------------------------------------------------------------
#define BM 128
#define BN 128
#define BKK 16

__global__ void __launch_bounds__(256)
k_gemm(const float* __restrict__ Aext, const float* __restrict__ B,
       const float* __restrict__ bias, int M, int K, int Nc, int mode) {
    const float* __restrict__ A = Aext ? Aext : g_h;

    __shared__ float As[BKK][BM + 4];
    __shared__ float Bs[BKK][BN + 4];

    const int m0 = blockIdx.x * BM;
    const int n0 = blockIdx.y * BN;
    const int tid = threadIdx.x;
    const int tr = tid >> 4;    // 0..15
    const int tc = tid & 15;    // 0..15

    float acc[8][8];
#pragma unroll
    for (int i = 0; i < 8; i++)
#pragma unroll
        for (int j = 0; j < 8; j++) acc[i][j] = 0.f;

    for (int k0 = 0; k0 < K; k0 += BKK) {
        // A tile: 128x16 = 512 float4, 2 per thread, stored transposed
#pragma unroll
        for (int l = 0; l < 2; l++) {
            int f = tid * 2 + l;
            int row = f >> 2;
            int c4 = (f & 3) * 4;
            float4 v = make_float4(0.f, 0.f, 0.f, 0.f);
            int m = m0 + row;
            if (m < M) v = *(const float4*)(A + (size_t)m * K + k0 + c4);
            As[c4 + 0][row] = v.x;
            As[c4 + 1][row] = v.y;
            As[c4 + 2][row] = v.z;
            As[c4 + 3][row] = v.w;
        }
        // B tile: 16x128 = 512 float4, 2 per thread
#pragma unroll
        for (int l = 0; l < 2; l++) {
            int f = tid * 2 + l;
            int row = f >> 5;
            int c4 = (f & 31) * 4;
            float4 v = *(const float4*)(B + (size_t)(k0 + row) * Nc + n0 + c4);
            *(float4*)&Bs[row][c4] = v;
        }
        __syncthreads();

#pragma unroll
        for (int k = 0; k < BKK; k++) {
            float ra[8], rb[8];
            *(float4*)(ra)     = *(const float4*)&As[k][tr * 8];
            *(float4*)(ra + 4) = *(const float4*)&As[k][tr * 8 + 4];
            *(float4*)(rb)     = *(const float4*)&Bs[k][tc * 8];
            *(float4*)(rb + 4) = *(const float4*)&Bs[k][tc * 8 + 4];
#pragma unroll
            for (int i = 0; i < 8; i++)
#pragma unroll
                for (int j = 0; j < 8; j++)
                    acc[i][j] += ra[i] * rb[j];
        }
        __syncthreads();
    }

    // Epilogue
    const int nbase = n0 + tc * 8;
    float bb[8];
    if (mode != 1) {
#pragma unroll
        for (int j = 0; j < 8; j++) bb[j] = bias[nbase + j];
    }

#pragma unroll
    for (int i = 0; i < 8; i++) {
        int m = m0 + tr * 8 + i;
        if (m >= M) break;
        size_t off = (size_t)m * Nc + nbase;
        if (mode == 0) {
            float4 v0, v1;
            v0.x = acc[i][0] + bb[0]; v0.y = acc[i][1] + bb[1];
            v0.z = acc[i][2] + bb[2]; v0.w = acc[i][3] + bb[3];
            v1.x = acc[i][4] + bb[4]; v1.y = acc[i][5] + bb[5];
            v1.z = acc[i][6] + bb[6]; v1.w = acc[i][7] + bb[7];
            *(float4*)(g_h + off) = v0;
            *(float4*)(g_h + off + 4) = v1;
        } else if (mode == 1) {
            float d = g_dis[m];
            float4 v0, v1;
            v0.x = acc[i][0] * d; v0.y = acc[i][1] * d;
            v0.z = acc[i][2] * d; v0.w = acc[i][3] * d;
            v1.x = acc[i][4] * d; v1.y = acc[i][5] * d;
            v1.z = acc[i][6] * d; v1.w = acc[i][7] * d;
            *(float4*)(g_hw + off) = v0;
            *(float4*)(g_hw + off + 4) = v1;
            *(float4*)(g_agg + off) = v0;      // self-loop init
            *(float4*)(g_agg + off + 4) = v1;
        } else {
            float4 v0, v1;
            v0.x = fmaxf(acc[i][0] + bb[0], 0.f); v0.y = fmaxf(acc[i][1] + bb[1], 0.f);
            v0.z = fmaxf(acc[i][2] + bb[2], 0.f); v0.w = fmaxf(acc[i][3] + bb[3], 0.f);
            v1.x = fmaxf(acc[i][4] + bb[4], 0.f); v1.y = fmaxf(acc[i][5] + bb[5], 0.f);
            v1.z = fmaxf(acc[i][6] + bb[6], 0.f); v1.w = fmaxf(acc[i][7] + bb[7], 0.f);
            *(float4*)(g_h1 + off) = v0;
            *(float4*)(g_h1 + off + 4) = v1;
        }
    }
}

// ---------------------------------------------------------------------------
// Edge scatter: warp per edge. Gather one 1KB row, vector-atomic into target.
// atomicAdd(float4*,float4): sm_90+ intrinsic -> vector RED, no return trip.
// ---------------------------------------------------------------------------
__global__ void __launch_bounds__(256)
k_scatter(const void* __restrict__ ei, int E, int N) {
    int warp = (blockIdx.x * blockDim.x + threadIdx.x) >> 5;
    if (warp >= E) return;
    int lane = threadIdx.x & 31;
    int is32 = g_is32;

    int r = edge_at(ei, warp, is32);
    int c = edge_at(ei, (size_t)E + warp, is32);
    if ((unsigned)r >= (unsigned)N || (unsigned)c >= (unsigned)N) return;

    const float4* __restrict__ src = (const float4*)(g_hw + (size_t)r * HID);
    float4*                    dst = (float4*)(g_agg + (size_t)c * HID);

    float4 v0 = __ldg(src + lane);
    float4 v1 = __ldg(src + lane + 32);
    atomicAdd(dst + lane, v0);
    atomicAdd(dst + lane + 32, v1);
}

// ---------------------------------------------------------------------------
// Finish conv layer: h = relu(LN(agg*dis + conv_b) * g + b), warp per node
// ---------------------------------------------------------------------------
__global__ void __launch_bounds__(256)
k_finish(const float* __restrict__ cb, const float* __restrict__ lg,
         const float* __restrict__ lb, int n) {
    int node = (blockIdx.x * blockDim.x + threadIdx.x) >> 5;
    if (node >= n) return;
    int lane = threadIdx.x & 31;
    size_t base = (size_t)node * HID;

    float d = g_dis[node];
    float4 a0 = *(const float4*)(g_agg + base + lane * 4);
    float4 a1 = *(const float4*)(g_agg + base + lane * 4 + 128);
    float4 c0 = ((const float4*)cb)[lane];
    float4 c1 = ((const float4*)cb)[lane + 32];

    float v[8];
    v[0] = a0.x * d + c0.x; v[1] = a0.y * d + c0.y;
    v[2] = a0.z * d + c0.z; v[3] = a0.w * d + c0.w;
    v[4] = a1.x * d + c1.x; v[5] = a1.y * d + c1.y;
    v[6] = a1.z * d + c1.z; v[7] = a1.w * d + c1.w;

    float s = 0.f, sq = 0.f;
#pragma unroll
    for (int i = 0; i < 8; i++) { s += v[i]; sq += v[i] * v[i]; }
#pragma unroll
    for (int o = 16; o > 0; o >>= 1) {
        s  += __shfl_xor_sync(0xffffffffu, s, o);
        sq += __shfl_xor_sync(0xffffffffu, sq, o);
    }
    float mu = s * (1.f / HID);
    float var = sq * (1.f / HID) - mu * mu;
    float rs = rsqrtf(var + LN_EPS);

    float4 g0 = ((const float4*)lg)[lane];
    float4 g1 = ((const float4*)lg)[lane + 32];
    float4 b0 = ((const float4*)lb)[lane];
    float4 b1 = ((const float4*)lb)[lane + 32];

    float4 o0, o1;
    o0.x = fmaxf((v[0] - mu) * rs * g0.x + b0.x, 0.f);
    o0.y = fmaxf((v[1] - mu) * rs * g0.y + b0.y, 0.f);
    o0.z = fmaxf((v[2] - mu) * rs * g0.z + b0.z, 0.f);
    o0.w = fmaxf((v[3] - mu) * rs * g0.w + b0.w, 0.f);
    o1.x = fmaxf((v[4] - mu) * rs * g1.x + b1.x, 0.f);
    o1.y = fmaxf((v[5] - mu) * rs * g1.y + b1.y, 0.f);
    o1.z = fmaxf((v[6] - mu) * rs * g1.z + b1.z, 0.f);
    o1.w = fmaxf((v[7] - mu) * rs * g1.w + b1.w, 0.f);

    *(float4*)(g_h + base + lane * 4) = o0;
    *(float4*)(g_h + base + lane * 4 + 128) = o1;
}

// ---------------------------------------------------------------------------
// lin2: out[n] = h1[n,:] . w + b, warp per node (128-dot)
// ---------------------------------------------------------------------------
__global__ void __launch_bounds__(256)
k_lin2(const float* __restrict__ w, const float* __restrict__ b,
       float* __restrict__ out, int n) {
    int node = (blockIdx.x * blockDim.x + threadIdx.x) >> 5;
    if (node >= n) return;
    int lane = threadIdx.x & 31;

    float4 h = *(const float4*)(g_h1 + (size_t)node * (HID / 2) + lane * 4);
    float4 wv = ((const float4*)w)[lane];
    float s = h.x * wv.x + h.y * wv.y + h.z * wv.z + h.w * wv.w;
#pragma unroll
    for (int o = 16; o > 0; o >>= 1)
        s += __shfl_xor_sync(0xffffffffu, s, o);
    if (lane == 0) out[node] = s + b[0];
}

// ---------------------------------------------------------------------------
// Launch
// ---------------------------------------------------------------------------
extern "C" void kernel_launch(void* const* d_in, const int* in_sizes, int n_in,
                              void* d_out, int out_size) {
    const float* x      = (const float*)d_in[0];
    const void*  ei     = d_in[1];                 // int32 or int64 — probed
    const float* enc_w  = (const float*)d_in[2];
    const float* enc_b  = (const float*)d_in[3];
    const float* conv_w = (const float*)d_in[4];
    const float* conv_b = (const float*)d_in[5];
    const float* ln_g   = (const float*)d_in[6];
    const float* ln_b   = (const float*)d_in[7];
    const float* lin1_w = (const float*)d_in[8];
    const float* lin1_b = (const float*)d_in[9];
    const float* lin2_w = (const float*)d_in[10];
    const float* lin2_b = (const float*)d_in[11];
    float* out = (float*)d_out;

    const int N = in_sizes[0] / IN_C;    // 100000
    const int E = in_sizes[1] / 2;       // 1600000

    // Probe edge_index dtype (deterministic; depends only on input content).
    // nsamp int64 reads = 2*nsamp int32 slots, safely within 2*E elements.
    int nsamp = (E >= 1024) ? 1024 : (E > 0 ? E : 1);
    k_detect<<<1, 256>>>((const long long*)ei, nsamp, N);

    // Degree + normalization (recomputed every call: deterministic work)
    k_deg_init<<<(N + 255) / 256, 256>>>(N);
    k_deg_count<<<(E + 255) / 256, 256>>>(ei, E, N);
    k_dis<<<(N + 255) / 256, 256>>>(N);

    dim3 g_enc((N + BM - 1) / BM, HID / BN);
    dim3 g_conv((N + BM - 1) / BM, HID / BN);
    dim3 g_lin1((N + BM - 1) / BM, (HID / 2) / BN);

    // Encoder: g_h = x @ enc_w + enc_b
    k_gemm<<<g_enc, 256>>>(x, enc_w, enc_b, N, IN_C, HID, 0);

    const int scatter_blocks = (int)(((size_t)E * 32 + 255) / 256);
    const int node_warp_blocks = (N * 32 + 255) / 256;

    for (int i = 0; i < NLAYERS; i++) {
        // hw = (g_h @ W_i) * dis  ;  agg initialized with self-loop term
        k_gemm<<<g_conv, 256>>>(nullptr, conv_w + (size_t)i * HID * HID,
                                nullptr, N, HID, HID, 1);
        // agg[col] += hw[row]
        k_scatter<<<scatter_blocks, 256>>>(ei, E, N);
        // h = relu(LN(agg*dis + b))
        k_finish<<<node_warp_blocks, 256>>>(conv_b + (size_t)i * HID,
                                            ln_g + (size_t)i * HID,
                                            ln_b + (size_t)i * HID, N);
    }

    // lin1 (+relu), then lin2
    k_gemm<<<g_lin1, 256>>>(nullptr, lin1_w, lin1_b, N, HID, HID / 2, 2);
    k_lin2<<<node_warp_blocks, 256>>>(lin2_w, lin2_b, out, N);
}

// round 11
// speedup vs baseline: 1.5958x; 1.5955x over previous
#include <cuda_runtime.h>
#include <cstdint>

// ---------------------------------------------------------------------------
// StressGCN: 4-layer GCN, N=100000 nodes, E=1.6M edges, IN_C=128, HID=256.
// h = relu(LN(agg(h@W)*dis + b)) x4, bracketed by encoder / lin1+relu / lin2.
// agg[c] = sum_{(r,c) in edges} hw[r] + hw[c],   hw = (h@W)*dis (pre-scaled)
// Aggregation is CSR-based gather (built once per call), no float atomics.
// ---------------------------------------------------------------------------

#define NNODES   100000
#define EMAX     1700000
#define IN_C     128
#define HID      256
#define NLAYERS  4
#define LN_EPS   1e-5f

// Scratch (device globals: allocation is forbidden)
__device__ float g_h  [(size_t)NNODES * HID];      // current features
__device__ float g_hw [(size_t)NNODES * HID];      // scaled h@W (gather source)
__device__ float g_h1 [(size_t)NNODES * (HID/2)];  // lin1 output
__device__ float g_dis[NNODES];
__device__ int   g_deg[NNODES];                    // 1 + in-degree
__device__ int   g_rowptr[NNODES + 1];
__device__ int   g_cursor[NNODES];
__device__ int   g_blocksum[1024];
__device__ int   g_csr[EMAX];                      // source node per edge slot
__device__ int   g_is32;                           // 1 if edge_index is int32

// ---------------------------------------------------------------------------
// Edge-index dtype probe (int64 vs int32 read as int64 -> out-of-range)
// ---------------------------------------------------------------------------
__global__ void k_detect(const long long* __restrict__ ei, int nsamp, int N) {
    __shared__ int bad;
    if (threadIdx.x == 0) bad = 0;
    __syncthreads();
    for (int i = threadIdx.x; i < nsamp; i += blockDim.x) {
        long long v = ei[i];
        if (v < 0 || v >= (long long)N) bad = 1;
    }
    __syncthreads();
    if (threadIdx.x == 0) g_is32 = bad;
}

__device__ __forceinline__ int edge_at(const void* ei, size_t pos, int is32) {
    return is32 ? ((const int*)ei)[pos]
                : (int)(((const long long*)ei)[pos]);
}

// ---------------------------------------------------------------------------
// Degree / normalization / CSR build
// ---------------------------------------------------------------------------
__global__ void k_deg_init(int n) {
    int i = blockIdx.x * blockDim.x + threadIdx.x;
    if (i < n) g_deg[i] = 1;  // self loop
}

__global__ void k_deg_count(const void* __restrict__ ei, int E, int N) {
    int e = blockIdx.x * blockDim.x + threadIdx.x;
    if (e >= E) return;
    int c = edge_at(ei, (size_t)E + e, g_is32);   // target
    if ((unsigned)c < (unsigned)N)
        atomicAdd(&g_deg[c], 1);
}

__global__ void k_dis(int n) {
    int i = blockIdx.x * blockDim.x + threadIdx.x;
    if (i < n) g_dis[i] = rsqrtf((float)g_deg[i]);
}

// Exclusive scan of (deg-1) [edge-only degree], 3-pass block scan.
__global__ void k_scan1(int n) {
    __shared__ int s[256];
    int idx = blockIdx.x * 256 + threadIdx.x;
    int v = (idx < n) ? (g_deg[idx] - 1) : 0;
    s[threadIdx.x] = v;
    __syncthreads();
#pragma unroll
    for (int off = 1; off < 256; off <<= 1) {
        int t = (threadIdx.x >= off) ? s[threadIdx.x - off] : 0;
        __syncthreads();
        s[threadIdx.x] += t;
        __syncthreads();
    }
    if (idx < n) g_rowptr[idx] = s[threadIdx.x] - v;   // exclusive
    if (threadIdx.x == 255) g_blocksum[blockIdx.x] = s[255];
}

__global__ void k_scan2(int nb, int N) {
    __shared__ int s[1024];
    int tid = threadIdx.x;
    int v = (tid < nb) ? g_blocksum[tid] : 0;
    s[tid] = v;
    __syncthreads();
#pragma unroll
    for (int off = 1; off < 1024; off <<= 1) {
        int t = (tid >= off) ? s[tid - off] : 0;
        __syncthreads();
        s[tid] += t;
        __syncthreads();
    }
    if (tid < nb) g_blocksum[tid] = s[tid] - v;        // exclusive
    if (tid == nb - 1) g_rowptr[N] = s[tid];           // total edge count
}

__global__ void k_scan3(int n) {
    int idx = blockIdx.x * blockDim.x + threadIdx.x;
    if (idx < n) {
        int r = g_rowptr[idx] + g_blocksum[blockIdx.x];
        g_rowptr[idx] = r;
        g_cursor[idx] = r;
    }
}

__global__ void k_fill(const void* __restrict__ ei, int E, int N) {
    int e = blockIdx.x * blockDim.x + threadIdx.x;
    if (e >= E) return;
    int is32 = g_is32;
    int r = edge_at(ei, e, is32);
    int c = edge_at(ei, (size_t)E + e, is32);
    if ((unsigned)r >= (unsigned)N || (unsigned)c >= (unsigned)N) return;
    int pos = atomicAdd(&g_cursor[c], 1);
    if (pos < EMAX) g_csr[pos] = r;
}

// ---------------------------------------------------------------------------
// SGEMM: C[M,Nc] = A[M,K] @ B[K,Nc], tiled 128x128x16, 256 threads, 8x8/thread
// mode 0: g_h  = C + bias               (encoder)
// mode 1: g_hw = C * dis[m]             (conv: pre-scale only)
// mode 2: g_h1 = relu(C + bias)         (lin1)
// Aext == nullptr -> A = g_h
// ---------------------------------------------------------------------------
#define BM 128
#define BN 128
#define BKK 16

__global__ void __launch_bounds__(256)
k_gemm(const float* __restrict__ Aext, const float* __restrict__ B,
       const float* __restrict__ bias, int M, int K, int Nc, int mode) {
    const float* __restrict__ A = Aext ? Aext : g_h;

    __shared__ float As[BKK][BM + 4];
    __shared__ float Bs[BKK][BN + 4];

    const int m0 = blockIdx.x * BM;
    const int n0 = blockIdx.y * BN;
    const int tid = threadIdx.x;
    const int tr = tid >> 4;    // 0..15
    const int tc = tid & 15;    // 0..15

    float acc[8][8];
#pragma unroll
    for (int i = 0; i < 8; i++)
#pragma unroll
        for (int j = 0; j < 8; j++) acc[i][j] = 0.f;

    for (int k0 = 0; k0 < K; k0 += BKK) {
#pragma unroll
        for (int l = 0; l < 2; l++) {
            int f = tid * 2 + l;
            int row = f >> 2;
            int c4 = (f & 3) * 4;
            float4 v = make_float4(0.f, 0.f, 0.f, 0.f);
            int m = m0 + row;
            if (m < M) v = *(const float4*)(A + (size_t)m * K + k0 + c4);
            As[c4 + 0][row] = v.x;
            As[c4 + 1][row] = v.y;
            As[c4 + 2][row] = v.z;
            As[c4 + 3][row] = v.w;
        }
#pragma unroll
        for (int l = 0; l < 2; l++) {
            int f = tid * 2 + l;
            int row = f >> 5;
            int c4 = (f & 31) * 4;
            float4 v = *(const float4*)(B + (size_t)(k0 + row) * Nc + n0 + c4);
            *(float4*)&Bs[row][c4] = v;
        }
        __syncthreads();

#pragma unroll
        for (int k = 0; k < BKK; k++) {
            float ra[8], rb[8];
            *(float4*)(ra)     = *(const float4*)&As[k][tr * 8];
            *(float4*)(ra + 4) = *(const float4*)&As[k][tr * 8 + 4];
            *(float4*)(rb)     = *(const float4*)&Bs[k][tc * 8];
            *(float4*)(rb + 4) = *(const float4*)&Bs[k][tc * 8 + 4];
#pragma unroll
            for (int i = 0; i < 8; i++)
#pragma unroll
                for (int j = 0; j < 8; j++)
                    acc[i][j] += ra[i] * rb[j];
        }
        __syncthreads();
    }

    const int nbase = n0 + tc * 8;
    float bb[8];
    if (mode != 1) {
#pragma unroll
        for (int j = 0; j < 8; j++) bb[j] = bias[nbase + j];
    }

#pragma unroll
    for (int i = 0; i < 8; i++) {
        int m = m0 + tr * 8 + i;
        if (m >= M) break;
        size_t off = (size_t)m * Nc + nbase;
        if (mode == 0) {
            float4 v0, v1;
            v0.x = acc[i][0] + bb[0]; v0.y = acc[i][1] + bb[1];
            v0.z = acc[i][2] + bb[2]; v0.w = acc[i][3] + bb[3];
            v1.x = acc[i][4] + bb[4]; v1.y = acc[i][5] + bb[5];
            v1.z = acc[i][6] + bb[6]; v1.w = acc[i][7] + bb[7];
            *(float4*)(g_h + off) = v0;
            *(float4*)(g_h + off + 4) = v1;
        } else if (mode == 1) {
            float d = g_dis[m];
            float4 v0, v1;
            v0.x = acc[i][0] * d; v0.y = acc[i][1] * d;
            v0.z = acc[i][2] * d; v0.w = acc[i][3] * d;
            v1.x = acc[i][4] * d; v1.y = acc[i][5] * d;
            v1.z = acc[i][6] * d; v1.w = acc[i][7] * d;
            *(float4*)(g_hw + off) = v0;
            *(float4*)(g_hw + off + 4) = v1;
        } else {
            float4 v0, v1;
            v0.x = fmaxf(acc[i][0] + bb[0], 0.f); v0.y = fmaxf(acc[i][1] + bb[1], 0.f);
            v0.z = fmaxf(acc[i][2] + bb[2], 0.f); v0.w = fmaxf(acc[i][3] + bb[3], 0.f);
            v1.x = fmaxf(acc[i][4] + bb[4], 0.f); v1.y = fmaxf(acc[i][5] + bb[5], 0.f);
            v1.z = fmaxf(acc[i][6] + bb[6], 0.f); v1.w = fmaxf(acc[i][7] + bb[7], 0.f);
            *(float4*)(g_h1 + off) = v0;
            *(float4*)(g_h1 + off + 4) = v1;
        }
    }
}

// ---------------------------------------------------------------------------
// Fused aggregate + finish: warp per node.
//   acc = hw[node] + sum_{r in CSR row} hw[r]        (register accumulation)
//   h[node] = relu(LN(acc*dis + conv_b) * g + b)
// Unrolled by 2 neighbors -> 4 outstanding float4 loads per lane.
// ---------------------------------------------------------------------------
__global__ void __launch_bounds__(256)
k_agg_finish(const float* __restrict__ cb, const float* __restrict__ lg,
             const float* __restrict__ lb, int n) {
    int node = (blockIdx.x * blockDim.x + threadIdx.x) >> 5;
    if (node >= n) return;
    int lane = threadIdx.x & 31;
    size_t base = (size_t)node * HID;

    // self-loop init
    float4 a0 = *(const float4*)(g_hw + base + lane * 4);
    float4 a1 = *(const float4*)(g_hw + base + lane * 4 + 128);

    int e   = g_rowptr[node];
    int end = g_rowptr[node + 1];

    for (; e + 1 < end; e += 2) {
        int r0 = __ldg(&g_csr[e]);
        int r1 = __ldg(&g_csr[e + 1]);
        const float4* s0 = (const float4*)(g_hw + (size_t)r0 * HID);
        const float4* s1 = (const float4*)(g_hw + (size_t)r1 * HID);
        float4 u0 = __ldg(s0 + lane);
        float4 u1 = __ldg(s0 + lane + 32);
        float4 w0 = __ldg(s1 + lane);
        float4 w1 = __ldg(s1 + lane + 32);
        a0.x += u0.x + w0.x; a0.y += u0.y + w0.y;
        a0.z += u0.z + w0.z; a0.w += u0.w + w0.w;
        a1.x += u1.x + w1.x; a1.y += u1.y + w1.y;
        a1.z += u1.z + w1.z; a1.w += u1.w + w1.w;
    }
    if (e < end) {
        int r0 = __ldg(&g_csr[e]);
        const float4* s0 = (const float4*)(g_hw + (size_t)r0 * HID);
        float4 u0 = __ldg(s0 + lane);
        float4 u1 = __ldg(s0 + lane + 32);
        a0.x += u0.x; a0.y += u0.y; a0.z += u0.z; a0.w += u0.w;
        a1.x += u1.x; a1.y += u1.y; a1.z += u1.z; a1.w += u1.w;
    }

    // finish: v = a*dis + conv_b; LN; relu
    float d = g_dis[node];
    float4 c0 = ((const float4*)cb)[lane];
    float4 c1 = ((const float4*)cb)[lane + 32];

    float v[8];
    v[0] = a0.x * d + c0.x; v[1] = a0.y * d + c0.y;
    v[2] = a0.z * d + c0.z; v[3] = a0.w * d + c0.w;
    v[4] = a1.x * d + c1.x; v[5] = a1.y * d + c1.y;
    v[6] = a1.z * d + c1.z; v[7] = a1.w * d + c1.w;

    float s = 0.f, sq = 0.f;
#pragma unroll
    for (int i = 0; i < 8; i++) { s += v[i]; sq += v[i] * v[i]; }
#pragma unroll
    for (int o = 16; o > 0; o >>= 1) {
        s  += __shfl_xor_sync(0xffffffffu, s, o);
        sq += __shfl_xor_sync(0xffffffffu, sq, o);
    }
    float mu = s * (1.f / HID);
    float var = sq * (1.f / HID) - mu * mu;
    float rs = rsqrtf(var + LN_EPS);

    float4 g0 = ((const float4*)lg)[lane];
    float4 g1 = ((const float4*)lg)[lane + 32];
    float4 b0 = ((const float4*)lb)[lane];
    float4 b1 = ((const float4*)lb)[lane + 32];

    float4 o0, o1;
    o0.x = fmaxf((v[0] - mu) * rs * g0.x + b0.x, 0.f);
    o0.y = fmaxf((v[1] - mu) * rs * g0.y + b0.y, 0.f);
    o0.z = fmaxf((v[2] - mu) * rs * g0.z + b0.z, 0.f);
    o0.w = fmaxf((v[3] - mu) * rs * g0.w + b0.w, 0.f);
    o1.x = fmaxf((v[4] - mu) * rs * g1.x + b1.x, 0.f);
    o1.y = fmaxf((v[5] - mu) * rs * g1.y + b1.y, 0.f);
    o1.z = fmaxf((v[6] - mu) * rs * g1.z + b1.z, 0.f);
    o1.w = fmaxf((v[7] - mu) * rs * g1.w + b1.w, 0.f);

    *(float4*)(g_h + base + lane * 4) = o0;
    *(float4*)(g_h + base + lane * 4 + 128) = o1;
}

// ---------------------------------------------------------------------------
// lin2: out[n] = h1[n,:] . w + b, warp per node (128-dot)
// ---------------------------------------------------------------------------
__global__ void __launch_bounds__(256)
k_lin2(const float* __restrict__ w, const float* __restrict__ b,
       float* __restrict__ out, int n) {
    int node = (blockIdx.x * blockDim.x + threadIdx.x) >> 5;
    if (node >= n) return;
    int lane = threadIdx.x & 31;

    float4 h = *(const float4*)(g_h1 + (size_t)node * (HID / 2) + lane * 4);
    float4 wv = ((const float4*)w)[lane];
    float s = h.x * wv.x + h.y * wv.y + h.z * wv.z + h.w * wv.w;
#pragma unroll
    for (int o = 16; o > 0; o >>= 1)
        s += __shfl_xor_sync(0xffffffffu, s, o);
    if (lane == 0) out[node] = s + b[0];
}

// ---------------------------------------------------------------------------
// Launch
// ---------------------------------------------------------------------------
extern "C" void kernel_launch(void* const* d_in, const int* in_sizes, int n_in,
                              void* d_out, int out_size) {
    const float* x      = (const float*)d_in[0];
    const void*  ei     = d_in[1];                 // int32 or int64 — probed
    const float* enc_w  = (const float*)d_in[2];
    const float* enc_b  = (const float*)d_in[3];
    const float* conv_w = (const float*)d_in[4];
    const float* conv_b = (const float*)d_in[5];
    const float* ln_g   = (const float*)d_in[6];
    const float* ln_b   = (const float*)d_in[7];
    const float* lin1_w = (const float*)d_in[8];
    const float* lin1_b = (const float*)d_in[9];
    const float* lin2_w = (const float*)d_in[10];
    const float* lin2_b = (const float*)d_in[11];
    float* out = (float*)d_out;

    const int N = in_sizes[0] / IN_C;    // 100000
    const int E = in_sizes[1] / 2;       // 1600000

    int nsamp = (E >= 1024) ? 1024 : (E > 0 ? E : 1);
    k_detect<<<1, 256>>>((const long long*)ei, nsamp, N);

    // Degree + normalization + CSR (recomputed every call: deterministic)
    const int nblk = (N + 255) / 256;
    k_deg_init<<<nblk, 256>>>(N);
    k_deg_count<<<(E + 255) / 256, 256>>>(ei, E, N);
    k_dis<<<nblk, 256>>>(N);
    k_scan1<<<nblk, 256>>>(N);
    k_scan2<<<1, 1024>>>(nblk, N);
    k_scan3<<<nblk, 256>>>(N);
    k_fill<<<(E + 255) / 256, 256>>>(ei, E, N);

    dim3 g_enc((N + BM - 1) / BM, HID / BN);
    dim3 g_conv((N + BM - 1) / BM, HID / BN);
    dim3 g_lin1((N + BM - 1) / BM, (HID / 2) / BN);

    // Encoder: g_h = x @ enc_w + enc_b
    k_gemm<<<g_enc, 256>>>(x, enc_w, enc_b, N, IN_C, HID, 0);

    const int node_warp_blocks = (N * 32 + 255) / 256;

    for (int i = 0; i < NLAYERS; i++) {
        // hw = (g_h @ W_i) * dis
        k_gemm<<<g_conv, 256>>>(nullptr, conv_w + (size_t)i * HID * HID,
                                nullptr, N, HID, HID, 1);
        // h = relu(LN((hw[node] + sum_neighbors hw)*dis + b))
        k_agg_finish<<<node_warp_blocks, 256>>>(conv_b + (size_t)i * HID,
                                                ln_g + (size_t)i * HID,
                                                ln_b + (size_t)i * HID, N);
    }

    // lin1 (+relu), then lin2
    k_gemm<<<g_lin1, 256>>>(nullptr, lin1_w, lin1_b, N, HID, HID / 2, 2);
    k_lin2<<<node_warp_blocks, 256>>>(lin2_w, lin2_b, out, N);
}

// round 12
// speedup vs baseline: 2.6256x; 1.6453x over previous
#include <cuda_runtime.h>
#include <cstdint>

// ---------------------------------------------------------------------------
// StressGCN: 4-layer GCN, N=100000 nodes, E=1.6M edges, IN_C=128, HID=256.
// h = relu(LN(agg(h@W)*dis + b)) x4, bracketed by encoder / lin1+relu / lin2.
// Aggregation: CSR gather (built once/call). Big GEMMs: tf32 tensor cores.
// ---------------------------------------------------------------------------

#define NNODES   100000
#define EMAX     1700000
#define IN_C     128
#define HID      256
#define NLAYERS  4
#define LN_EPS   1e-5f

// Scratch (device globals: allocation is forbidden)
__device__ float g_h  [(size_t)NNODES * HID];      // current features
__device__ float g_hw [(size_t)NNODES * HID];      // scaled h@W (gather source)
__device__ float g_h1 [(size_t)NNODES * (HID/2)];  // lin1 output
__device__ float g_dis[NNODES];
__device__ int   g_deg[NNODES];                    // 1 + in-degree
__device__ int   g_rowptr[NNODES + 1];
__device__ int   g_cursor[NNODES];
__device__ int   g_blocksum[1024];
__device__ int   g_csr[EMAX];                      // source node per edge slot
__device__ int   g_is32;                           // 1 if edge_index is int32

// ---------------------------------------------------------------------------
// Edge-index dtype probe (int64 vs int32 read as int64 -> out-of-range)
// ---------------------------------------------------------------------------
__global__ void k_detect(const long long* __restrict__ ei, int nsamp, int N) {
    __shared__ int bad;
    if (threadIdx.x == 0) bad = 0;
    __syncthreads();
    for (int i = threadIdx.x; i < nsamp; i += blockDim.x) {
        long long v = ei[i];
        if (v < 0 || v >= (long long)N) bad = 1;
    }
    __syncthreads();
    if (threadIdx.x == 0) g_is32 = bad;
}

__device__ __forceinline__ int edge_at(const void* ei, size_t pos, int is32) {
    return is32 ? ((const int*)ei)[pos]
                : (int)(((const long long*)ei)[pos]);
}

// ---------------------------------------------------------------------------
// Degree / normalization / CSR build
// ---------------------------------------------------------------------------
__global__ void k_deg_init(int n) {
    int i = blockIdx.x * blockDim.x + threadIdx.x;
    if (i < n) g_deg[i] = 1;  // self loop
}

__global__ void k_deg_count(const void* __restrict__ ei, int E, int N) {
    int e = blockIdx.x * blockDim.x + threadIdx.x;
    if (e >= E) return;
    int c = edge_at(ei, (size_t)E + e, g_is32);   // target
    if ((unsigned)c < (unsigned)N)
        atomicAdd(&g_deg[c], 1);
}

__global__ void k_dis(int n) {
    int i = blockIdx.x * blockDim.x + threadIdx.x;
    if (i < n) g_dis[i] = rsqrtf((float)g_deg[i]);
}

// Exclusive scan of (deg-1) [edge-only degree], 3-pass block scan.
__global__ void k_scan1(int n) {
    __shared__ int s[256];
    int idx = blockIdx.x * 256 + threadIdx.x;
    int v = (idx < n) ? (g_deg[idx] - 1) : 0;
    s[threadIdx.x] = v;
    __syncthreads();
#pragma unroll
    for (int off = 1; off < 256; off <<= 1) {
        int t = (threadIdx.x >= off) ? s[threadIdx.x - off] : 0;
        __syncthreads();
        s[threadIdx.x] += t;
        __syncthreads();
    }
    if (idx < n) g_rowptr[idx] = s[threadIdx.x] - v;   // exclusive
    if (threadIdx.x == 255) g_blocksum[blockIdx.x] = s[255];
}

__global__ void k_scan2(int nb, int N) {
    __shared__ int s[1024];
    int tid = threadIdx.x;
    int v = (tid < nb) ? g_blocksum[tid] : 0;
    s[tid] = v;
    __syncthreads();
#pragma unroll
    for (int off = 1; off < 1024; off <<= 1) {
        int t = (tid >= off) ? s[tid - off] : 0;
        __syncthreads();
        s[tid] += t;
        __syncthreads();
    }
    if (tid < nb) g_blocksum[tid] = s[tid] - v;        // exclusive
    if (tid == nb - 1) g_rowptr[N] = s[tid];           // total edge count
}

__global__ void k_scan3(int n) {
    int idx = blockIdx.x * blockDim.x + threadIdx.x;
    if (idx < n) {
        int r = g_rowptr[idx] + g_blocksum[blockIdx.x];
        g_rowptr[idx] = r;
        g_cursor[idx] = r;
    }
}

__global__ void k_fill(const void* __restrict__ ei, int E, int N) {
    int e = blockIdx.x * blockDim.x + threadIdx.x;
    if (e >= E) return;
    int is32 = g_is32;
    int r = edge_at(ei, e, is32);
    int c = edge_at(ei, (size_t)E + e, is32);
    if ((unsigned)r >= (unsigned)N || (unsigned)c >= (unsigned)N) return;
    int pos = atomicAdd(&g_cursor[c], 1);
    if (pos < EMAX) g_csr[pos] = r;
}

// ---------------------------------------------------------------------------
// TF32 tensor-core GEMM: C[M,256] = A[M,K] @ B[K,256]
// Block tile 128x256x32, 256 threads = 8 warps (2m x 4n), warp tile 64x64,
// per warp 4(m) x 8(n) mma.m16n8k8 fragments.
// mode 0: g_h  = C + bias     (encoder)
// mode 1: g_hw = C * dis[m]   (conv pre-scale; A = g_h)
// A operands feed fp32 bits directly (HW uses top 19 bits: RZ-rounded tf32).
// ---------------------------------------------------------------------------
#define TBM 128
#define TBN 256
#define TBK 32
#define ASTRIDE 36   // 32 + 4: fragment LDS conflict-free, float4-aligned
#define BSTRIDE 264  // 256 + 8: fragment LDS conflict-free, float4-aligned

__global__ void __launch_bounds__(256, 1)
k_gemm_tf32(const float* __restrict__ Aext, const float* __restrict__ B,
            const float* __restrict__ bias, int M, int K, int mode) {
    const float* __restrict__ A = Aext ? Aext : g_h;

    __shared__ float As[TBM * ASTRIDE];   // [m][k]
    __shared__ float Bs[TBK * BSTRIDE];   // [k][n]

    const int tid  = threadIdx.x;
    const int lane = tid & 31;
    const int wid  = tid >> 5;
    const int wm0  = (wid & 1) * 64;      // warp m-origin in tile
    const int wn0  = (wid >> 1) * 64;     // warp n-origin in tile
    const int m0   = blockIdx.x * TBM;

    const int lq = lane >> 2;             // lane/4: 0..7
    const int lr = lane & 3;              // lane%4: 0..3

    float acc[4][8][4];
#pragma unroll
    for (int mt = 0; mt < 4; mt++)
#pragma unroll
        for (int nt = 0; nt < 8; nt++)
#pragma unroll
            for (int i = 0; i < 4; i++) acc[mt][nt][i] = 0.f;

    for (int k0 = 0; k0 < K; k0 += TBK) {
        // A tile: 128x32 floats = 1024 float4; 4 per thread
#pragma unroll
        for (int i = 0; i < 4; i++) {
            int f = i * 256 + tid;
            int row = f >> 3;
            int c4 = (f & 7) * 4;
            float4 v = make_float4(0.f, 0.f, 0.f, 0.f);
            int m = m0 + row;
            if (m < M) v = *(const float4*)(A + (size_t)m * K + k0 + c4);
            *(float4*)&As[row * ASTRIDE + c4] = v;
        }
        // B tile: 32x256 floats = 2048 float4; 8 per thread
#pragma unroll
        for (int i = 0; i < 8; i++) {
            int f = i * 256 + tid;
            int row = f >> 6;
            int c4 = (f & 63) * 4;
            float4 v = *(const float4*)(B + (size_t)(k0 + row) * TBN + c4);
            *(float4*)&Bs[row * BSTRIDE + c4] = v;
        }
        __syncthreads();

#pragma unroll
        for (int ks = 0; ks < 4; ks++) {
            const int kc = ks * 8;
            // A fragments: 4 m-tiles
            uint32_t af[4][4];
#pragma unroll
            for (int mt = 0; mt < 4; mt++) {
                int r0 = wm0 + mt * 16 + lq;
                af[mt][0] = __float_as_uint(As[(r0    ) * ASTRIDE + kc + lr    ]);
                af[mt][1] = __float_as_uint(As[(r0 + 8) * ASTRIDE + kc + lr    ]);
                af[mt][2] = __float_as_uint(As[(r0    ) * ASTRIDE + kc + lr + 4]);
                af[mt][3] = __float_as_uint(As[(r0 + 8) * ASTRIDE + kc + lr + 4]);
            }
            // B fragments: 8 n-tiles
            uint32_t bf[8][2];
#pragma unroll
            for (int nt = 0; nt < 8; nt++) {
                int col = wn0 + nt * 8 + lq;
                bf[nt][0] = __float_as_uint(Bs[(kc + lr    ) * BSTRIDE + col]);
                bf[nt][1] = __float_as_uint(Bs[(kc + lr + 4) * BSTRIDE + col]);
            }
#pragma unroll
            for (int mt = 0; mt < 4; mt++)
#pragma unroll
                for (int nt = 0; nt < 8; nt++) {
                    float* c = acc[mt][nt];
                    asm volatile(
                        "mma.sync.aligned.m16n8k8.row.col.f32.tf32.tf32.f32 "
                        "{%0,%1,%2,%3}, {%4,%5,%6,%7}, {%8,%9}, {%0,%1,%2,%3};"
                        : "+f"(c[0]), "+f"(c[1]), "+f"(c[2]), "+f"(c[3])
                        : "r"(af[mt][0]), "r"(af[mt][1]),
                          "r"(af[mt][2]), "r"(af[mt][3]),
                          "r"(bf[nt][0]), "r"(bf[nt][1]));
                }
        }
        __syncthreads();
    }

    // Epilogue. c0,c1 -> (row, col..col+1); c2,c3 -> (row+8, same cols)
#pragma unroll
    for (int mt = 0; mt < 4; mt++) {
        int r0 = m0 + wm0 + mt * 16 + lq;
        int r1 = r0 + 8;
        if (mode == 1) {
            float d0 = (r0 < M) ? g_dis[r0] : 0.f;
            float d1 = (r1 < M) ? g_dis[r1] : 0.f;
#pragma unroll
            for (int nt = 0; nt < 8; nt++) {
                int col = wn0 + nt * 8 + 2 * lr;
                float* c = acc[mt][nt];
                if (r0 < M) {
                    float2 v = make_float2(c[0] * d0, c[1] * d0);
                    *(float2*)(g_hw + (size_t)r0 * TBN + col) = v;
                }
                if (r1 < M) {
                    float2 v = make_float2(c[2] * d1, c[3] * d1);
                    *(float2*)(g_hw + (size_t)r1 * TBN + col) = v;
                }
            }
        } else {
#pragma unroll
            for (int nt = 0; nt < 8; nt++) {
                int col = wn0 + nt * 8 + 2 * lr;
                float2 bv = *(const float2*)(bias + col);
                float* c = acc[mt][nt];
                if (r0 < M) {
                    float2 v = make_float2(c[0] + bv.x, c[1] + bv.y);
                    *(float2*)(g_h + (size_t)r0 * TBN + col) = v;
                }
                if (r1 < M) {
                    float2 v = make_float2(c[2] + bv.x, c[3] + bv.y);
                    *(float2*)(g_h + (size_t)r1 * TBN + col) = v;
                }
            }
        }
    }
}

// ---------------------------------------------------------------------------
// SIMT SGEMM (kept for lin1: Nc=128): tiled 128x128x16
// mode 2: g_h1 = relu(C + bias), A = g_h
// ---------------------------------------------------------------------------
#define BM 128
#define BN 128
#define BKK 16

__global__ void __launch_bounds__(256)
k_gemm(const float* __restrict__ B, const float* __restrict__ bias,
       int M, int K, int Nc) {
    const float* __restrict__ A = g_h;

    __shared__ float As[BKK][BM + 4];
    __shared__ float Bs[BKK][BN + 4];

    const int m0 = blockIdx.x * BM;
    const int n0 = blockIdx.y * BN;
    const int tid = threadIdx.x;
    const int tr = tid >> 4;
    const int tc = tid & 15;

    float acc[8][8];
#pragma unroll
    for (int i = 0; i < 8; i++)
#pragma unroll
        for (int j = 0; j < 8; j++) acc[i][j] = 0.f;

    for (int k0 = 0; k0 < K; k0 += BKK) {
#pragma unroll
        for (int l = 0; l < 2; l++) {
            int f = tid * 2 + l;
            int row = f >> 2;
            int c4 = (f & 3) * 4;
            float4 v = make_float4(0.f, 0.f, 0.f, 0.f);
            int m = m0 + row;
            if (m < M) v = *(const float4*)(A + (size_t)m * K + k0 + c4);
            As[c4 + 0][row] = v.x;
            As[c4 + 1][row] = v.y;
            As[c4 + 2][row] = v.z;
            As[c4 + 3][row] = v.w;
        }
#pragma unroll
        for (int l = 0; l < 2; l++) {
            int f = tid * 2 + l;
            int row = f >> 5;
            int c4 = (f & 31) * 4;
            float4 v = *(const float4*)(B + (size_t)(k0 + row) * Nc + n0 + c4);
            *(float4*)&Bs[row][c4] = v;
        }
        __syncthreads();

#pragma unroll
        for (int k = 0; k < BKK; k++) {
            float ra[8], rb[8];
            *(float4*)(ra)     = *(const float4*)&As[k][tr * 8];
            *(float4*)(ra + 4) = *(const float4*)&As[k][tr * 8 + 4];
            *(float4*)(rb)     = *(const float4*)&Bs[k][tc * 8];
            *(float4*)(rb + 4) = *(const float4*)&Bs[k][tc * 8 + 4];
#pragma unroll
            for (int i = 0; i < 8; i++)
#pragma unroll
                for (int j = 0; j < 8; j++)
                    acc[i][j] += ra[i] * rb[j];
        }
        __syncthreads();
    }

    const int nbase = n0 + tc * 8;
    float bb[8];
#pragma unroll
    for (int j = 0; j < 8; j++) bb[j] = bias[nbase + j];

#pragma unroll
    for (int i = 0; i < 8; i++) {
        int m = m0 + tr * 8 + i;
        if (m >= M) break;
        size_t off = (size_t)m * Nc + nbase;
        float4 v0, v1;
        v0.x = fmaxf(acc[i][0] + bb[0], 0.f); v0.y = fmaxf(acc[i][1] + bb[1], 0.f);
        v0.z = fmaxf(acc[i][2] + bb[2], 0.f); v0.w = fmaxf(acc[i][3] + bb[3], 0.f);
        v1.x = fmaxf(acc[i][4] + bb[4], 0.f); v1.y = fmaxf(acc[i][5] + bb[5], 0.f);
        v1.z = fmaxf(acc[i][6] + bb[6], 0.f); v1.w = fmaxf(acc[i][7] + bb[7], 0.f);
        *(float4*)(g_h1 + off) = v0;
        *(float4*)(g_h1 + off + 4) = v1;
    }
}

// ---------------------------------------------------------------------------
// Fused aggregate + finish: warp per node.
//   acc = hw[node] + sum_{r in CSR row} hw[r]
//   h[node] = relu(LN(acc*dis + conv_b) * g + b)
// ---------------------------------------------------------------------------
__global__ void __launch_bounds__(256)
k_agg_finish(const float* __restrict__ cb, const float* __restrict__ lg,
             const float* __restrict__ lb, int n) {
    int node = (blockIdx.x * blockDim.x + threadIdx.x) >> 5;
    if (node >= n) return;
    int lane = threadIdx.x & 31;
    size_t base = (size_t)node * HID;

    float4 a0 = *(const float4*)(g_hw + base + lane * 4);
    float4 a1 = *(const float4*)(g_hw + base + lane * 4 + 128);

    int e   = g_rowptr[node];
    int end = g_rowptr[node + 1];

    for (; e + 1 < end; e += 2) {
        int r0 = __ldg(&g_csr[e]);
        int r1 = __ldg(&g_csr[e + 1]);
        const float4* s0 = (const float4*)(g_hw + (size_t)r0 * HID);
        const float4* s1 = (const float4*)(g_hw + (size_t)r1 * HID);
        float4 u0 = __ldg(s0 + lane);
        float4 u1 = __ldg(s0 + lane + 32);
        float4 w0 = __ldg(s1 + lane);
        float4 w1 = __ldg(s1 + lane + 32);
        a0.x += u0.x + w0.x; a0.y += u0.y + w0.y;
        a0.z += u0.z + w0.z; a0.w += u0.w + w0.w;
        a1.x += u1.x + w1.x; a1.y += u1.y + w1.y;
        a1.z += u1.z + w1.z; a1.w += u1.w + w1.w;
    }
    if (e < end) {
        int r0 = __ldg(&g_csr[e]);
        const float4* s0 = (const float4*)(g_hw + (size_t)r0 * HID);
        float4 u0 = __ldg(s0 + lane);
        float4 u1 = __ldg(s0 + lane + 32);
        a0.x += u0.x; a0.y += u0.y; a0.z += u0.z; a0.w += u0.w;
        a1.x += u1.x; a1.y += u1.y; a1.z += u1.z; a1.w += u1.w;
    }

    float d = g_dis[node];
    float4 c0 = ((const float4*)cb)[lane];
    float4 c1 = ((const float4*)cb)[lane + 32];

    float v[8];
    v[0] = a0.x * d + c0.x; v[1] = a0.y * d + c0.y;
    v[2] = a0.z * d + c0.z; v[3] = a0.w * d + c0.w;
    v[4] = a1.x * d + c1.x; v[5] = a1.y * d + c1.y;
    v[6] = a1.z * d + c1.z; v[7] = a1.w * d + c1.w;

    float s = 0.f, sq = 0.f;
#pragma unroll
    for (int i = 0; i < 8; i++) { s += v[i]; sq += v[i] * v[i]; }
#pragma unroll
    for (int o = 16; o > 0; o >>= 1) {
        s  += __shfl_xor_sync(0xffffffffu, s, o);
        sq += __shfl_xor_sync(0xffffffffu, sq, o);
    }
    float mu = s * (1.f / HID);
    float var = sq * (1.f / HID) - mu * mu;
    float rs = rsqrtf(var + LN_EPS);

    float4 g0 = ((const float4*)lg)[lane];
    float4 g1 = ((const float4*)lg)[lane + 32];
    float4 b0 = ((const float4*)lb)[lane];
    float4 b1 = ((const float4*)lb)[lane + 32];

    float4 o0, o1;
    o0.x = fmaxf((v[0] - mu) * rs * g0.x + b0.x, 0.f);
    o0.y = fmaxf((v[1] - mu) * rs * g0.y + b0.y, 0.f);
    o0.z = fmaxf((v[2] - mu) * rs * g0.z + b0.z, 0.f);
    o0.w = fmaxf((v[3] - mu) * rs * g0.w + b0.w, 0.f);
    o1.x = fmaxf((v[4] - mu) * rs * g1.x + b1.x, 0.f);
    o1.y = fmaxf((v[5] - mu) * rs * g1.y + b1.y, 0.f);
    o1.z = fmaxf((v[6] - mu) * rs * g1.z + b1.z, 0.f);
    o1.w = fmaxf((v[7] - mu) * rs * g1.w + b1.w, 0.f);

    *(float4*)(g_h + base + lane * 4) = o0;
    *(float4*)(g_h + base + lane * 4 + 128) = o1;
}

// ---------------------------------------------------------------------------
// lin2: out[n] = h1[n,:] . w + b, warp per node (128-dot)
// ---------------------------------------------------------------------------
__global__ void __launch_bounds__(256)
k_lin2(const float* __restrict__ w, const float* __restrict__ b,
       float* __restrict__ out, int n) {
    int node = (blockIdx.x * blockDim.x + threadIdx.x) >> 5;
    if (node >= n) return;
    int lane = threadIdx.x & 31;

    float4 h = *(const float4*)(g_h1 + (size_t)node * (HID / 2) + lane * 4);
    float4 wv = ((const float4*)w)[lane];
    float s = h.x * wv.x + h.y * wv.y + h.z * wv.z + h.w * wv.w;
#pragma unroll
    for (int o = 16; o > 0; o >>= 1)
        s += __shfl_xor_sync(0xffffffffu, s, o);
    if (lane == 0) out[node] = s + b[0];
}

// ---------------------------------------------------------------------------
// Launch
// ---------------------------------------------------------------------------
extern "C" void kernel_launch(void* const* d_in, const int* in_sizes, int n_in,
                              void* d_out, int out_size) {
    const float* x      = (const float*)d_in[0];
    const void*  ei     = d_in[1];                 // int32 or int64 — probed
    const float* enc_w  = (const float*)d_in[2];
    const float* enc_b  = (const float*)d_in[3];
    const float* conv_w = (const float*)d_in[4];
    const float* conv_b = (const float*)d_in[5];
    const float* ln_g   = (const float*)d_in[6];
    const float* ln_b   = (const float*)d_in[7];
    const float* lin1_w = (const float*)d_in[8];
    const float* lin1_b = (const float*)d_in[9];
    const float* lin2_w = (const float*)d_in[10];
    const float* lin2_b = (const float*)d_in[11];
    float* out = (float*)d_out;

    const int N = in_sizes[0] / IN_C;    // 100000
    const int E = in_sizes[1] / 2;       // 1600000

    int nsamp = (E >= 1024) ? 1024 : (E > 0 ? E : 1);
    k_detect<<<1, 256>>>((const long long*)ei, nsamp, N);

    // Degree + normalization + CSR (recomputed every call: deterministic)
    const int nblk = (N + 255) / 256;
    k_deg_init<<<nblk, 256>>>(N);
    k_deg_count<<<(E + 255) / 256, 256>>>(ei, E, N);
    k_dis<<<nblk, 256>>>(N);
    k_scan1<<<nblk, 256>>>(N);
    k_scan2<<<1, 1024>>>(nblk, N);
    k_scan3<<<nblk, 256>>>(N);
    k_fill<<<(E + 255) / 256, 256>>>(ei, E, N);

    const int tf32_blocks = (N + TBM - 1) / TBM;

    // Encoder: g_h = x @ enc_w + enc_b   (tf32, K=128)
    k_gemm_tf32<<<tf32_blocks, 256>>>(x, enc_w, enc_b, N, IN_C, 0);

    const int node_warp_blocks = (N * 32 + 255) / 256;

    for (int i = 0; i < NLAYERS; i++) {
        // hw = (g_h @ W_i) * dis   (tf32, K=256)
        k_gemm_tf32<<<tf32_blocks, 256>>>(nullptr,
                                          conv_w + (size_t)i * HID * HID,
                                          nullptr, N, HID, 1);
        // h = relu(LN((hw[node] + sum_neighbors hw)*dis + b))
        k_agg_finish<<<node_warp_blocks, 256>>>(conv_b + (size_t)i * HID,
                                                ln_g + (size_t)i * HID,
                                                ln_b + (size_t)i * HID, N);
    }

    // lin1 (+relu) SIMT, then lin2
    dim3 g_lin1((N + BM - 1) / BM, (HID / 2) / BN);
    k_gemm<<<g_lin1, 256>>>(lin1_w, lin1_b, N, HID, HID / 2);
    k_lin2<<<node_warp_blocks, 256>>>(lin2_w, lin2_b, out, N);
}

// round 13
// speedup vs baseline: 3.1752x; 1.2093x over previous
#include <cuda_runtime.h>
#include <cuda_fp16.h>
#include <cstdint>

// ---------------------------------------------------------------------------
// StressGCN: 4-layer GCN, N=100000 nodes, E=1.6M edges, IN_C=128, HID=256.
// h = relu(LN(agg(h@W)*dis + b)) x4, bracketed by encoder / lin1+relu / lin2.
// CSR gather aggregation; tf32 tensor-core GEMMs; fp16 gather source (g_hw)
// with fp32 accumulation.
// ---------------------------------------------------------------------------

#define NNODES   100000
#define EMAX     1700000
#define IN_C     128
#define HID      256
#define NLAYERS  4
#define LN_EPS   1e-5f

// Scratch (device globals: allocation is forbidden)
__device__ float  g_h  [(size_t)NNODES * HID];      // current features
__device__ __half g_hw [(size_t)NNODES * HID];      // scaled h@W, fp16 (gather)
__device__ float  g_h1 [(size_t)NNODES * (HID/2)];  // lin1 output
__device__ float  g_dis[NNODES];
__device__ int    g_deg[NNODES];                    // 1 + in-degree
__device__ int    g_rowptr[NNODES + 1];
__device__ int    g_cursor[NNODES];
__device__ int    g_blocksum[1024];
__device__ int    g_csr[EMAX];                      // source node per edge slot
__device__ int    g_is32;                           // 1 if edge_index is int32

// ---------------------------------------------------------------------------
// Edge-index dtype probe (int64 vs int32 read as int64 -> out-of-range)
// ---------------------------------------------------------------------------
__global__ void k_detect(const long long* __restrict__ ei, int nsamp, int N) {
    __shared__ int bad;
    if (threadIdx.x == 0) bad = 0;
    __syncthreads();
    for (int i = threadIdx.x; i < nsamp; i += blockDim.x) {
        long long v = ei[i];
        if (v < 0 || v >= (long long)N) bad = 1;
    }
    __syncthreads();
    if (threadIdx.x == 0) g_is32 = bad;
}

__device__ __forceinline__ int edge_at(const void* ei, size_t pos, int is32) {
    return is32 ? ((const int*)ei)[pos]
                : (int)(((const long long*)ei)[pos]);
}

// ---------------------------------------------------------------------------
// Degree / normalization / CSR build
// ---------------------------------------------------------------------------
__global__ void k_deg_init(int n) {
    int i = blockIdx.x * blockDim.x + threadIdx.x;
    if (i < n) g_deg[i] = 1;  // self loop
}

__global__ void k_deg_count(const void* __restrict__ ei, int E, int N) {
    int e = blockIdx.x * blockDim.x + threadIdx.x;
    if (e >= E) return;
    int c = edge_at(ei, (size_t)E + e, g_is32);   // target
    if ((unsigned)c < (unsigned)N)
        atomicAdd(&g_deg[c], 1);
}

__global__ void k_dis(int n) {
    int i = blockIdx.x * blockDim.x + threadIdx.x;
    if (i < n) g_dis[i] = rsqrtf((float)g_deg[i]);
}

// Exclusive scan of (deg-1) [edge-only degree], 3-pass block scan.
__global__ void k_scan1(int n) {
    __shared__ int s[256];
    int idx = blockIdx.x * 256 + threadIdx.x;
    int v = (idx < n) ? (g_deg[idx] - 1) : 0;
    s[threadIdx.x] = v;
    __syncthreads();
#pragma unroll
    for (int off = 1; off < 256; off <<= 1) {
        int t = (threadIdx.x >= off) ? s[threadIdx.x - off] : 0;
        __syncthreads();
        s[threadIdx.x] += t;
        __syncthreads();
    }
    if (idx < n) g_rowptr[idx] = s[threadIdx.x] - v;   // exclusive
    if (threadIdx.x == 255) g_blocksum[blockIdx.x] = s[255];
}

__global__ void k_scan2(int nb, int N) {
    __shared__ int s[1024];
    int tid = threadIdx.x;
    int v = (tid < nb) ? g_blocksum[tid] : 0;
    s[tid] = v;
    __syncthreads();
#pragma unroll
    for (int off = 1; off < 1024; off <<= 1) {
        int t = (tid >= off) ? s[tid - off] : 0;
        __syncthreads();
        s[tid] += t;
        __syncthreads();
    }
    if (tid < nb) g_blocksum[tid] = s[tid] - v;        // exclusive
    if (tid == nb - 1) g_rowptr[N] = s[tid];           // total edge count
}

__global__ void k_scan3(int n) {
    int idx = blockIdx.x * blockDim.x + threadIdx.x;
    if (idx < n) {
        int r = g_rowptr[idx] + g_blocksum[blockIdx.x];
        g_rowptr[idx] = r;
        g_cursor[idx] = r;
    }
}

__global__ void k_fill(const void* __restrict__ ei, int E, int N) {
    int e = blockIdx.x * blockDim.x + threadIdx.x;
    if (e >= E) return;
    int is32 = g_is32;
    int r = edge_at(ei, e, is32);
    int c = edge_at(ei, (size_t)E + e, is32);
    if ((unsigned)r >= (unsigned)N || (unsigned)c >= (unsigned)N) return;
    int pos = atomicAdd(&g_cursor[c], 1);
    if (pos < EMAX) g_csr[pos] = r;
}

// ---------------------------------------------------------------------------
// TF32 tensor-core GEMM: C[M,256] = A[M,K] @ B[K,256]
// Block tile 128x256x32, 256 threads = 8 warps (2m x 4n), warp tile 64x64,
// per warp 4(m) x 8(n) mma.m16n8k8 fragments.
// mode 0: g_h  = C + bias              (encoder, fp32 out)
// mode 1: g_hw = half(C * dis[m])      (conv pre-scale; A = g_h, fp16 out)
// ---------------------------------------------------------------------------
#define TBM 128
#define TBN 256
#define TBK 32
#define ASTRIDE 36   // 32 + 4: fragment LDS conflict-free, float4-aligned
#define BSTRIDE 264  // 256 + 8: fragment LDS conflict-free, float4-aligned

__global__ void __launch_bounds__(256, 1)
k_gemm_tf32(const float* __restrict__ Aext, const float* __restrict__ B,
            const float* __restrict__ bias, int M, int K, int mode) {
    const float* __restrict__ A = Aext ? Aext : g_h;

    __shared__ float As[TBM * ASTRIDE];   // [m][k]
    __shared__ float Bs[TBK * BSTRIDE];   // [k][n]

    const int tid  = threadIdx.x;
    const int lane = tid & 31;
    const int wid  = tid >> 5;
    const int wm0  = (wid & 1) * 64;      // warp m-origin in tile
    const int wn0  = (wid >> 1) * 64;     // warp n-origin in tile
    const int m0   = blockIdx.x * TBM;

    const int lq = lane >> 2;             // lane/4: 0..7
    const int lr = lane & 3;              // lane%4: 0..3

    float acc[4][8][4];
#pragma unroll
    for (int mt = 0; mt < 4; mt++)
#pragma unroll
        for (int nt = 0; nt < 8; nt++)
#pragma unroll
            for (int i = 0; i < 4; i++) acc[mt][nt][i] = 0.f;

    for (int k0 = 0; k0 < K; k0 += TBK) {
        // A tile: 128x32 floats = 1024 float4; 4 per thread
#pragma unroll
        for (int i = 0; i < 4; i++) {
            int f = i * 256 + tid;
            int row = f >> 3;
            int c4 = (f & 7) * 4;
            float4 v = make_float4(0.f, 0.f, 0.f, 0.f);
            int m = m0 + row;
            if (m < M) v = *(const float4*)(A + (size_t)m * K + k0 + c4);
            *(float4*)&As[row * ASTRIDE + c4] = v;
        }
        // B tile: 32x256 floats = 2048 float4; 8 per thread
#pragma unroll
        for (int i = 0; i < 8; i++) {
            int f = i * 256 + tid;
            int row = f >> 6;
            int c4 = (f & 63) * 4;
            float4 v = *(const float4*)(B + (size_t)(k0 + row) * TBN + c4);
            *(float4*)&Bs[row * BSTRIDE + c4] = v;
        }
        __syncthreads();

#pragma unroll
        for (int ks = 0; ks < 4; ks++) {
            const int kc = ks * 8;
            uint32_t af[4][4];
#pragma unroll
            for (int mt = 0; mt < 4; mt++) {
                int r0 = wm0 + mt * 16 + lq;
                af[mt][0] = __float_as_uint(As[(r0    ) * ASTRIDE + kc + lr    ]);
                af[mt][1] = __float_as_uint(As[(r0 + 8) * ASTRIDE + kc + lr    ]);
                af[mt][2] = __float_as_uint(As[(r0    ) * ASTRIDE + kc + lr + 4]);
                af[mt][3] = __float_as_uint(As[(r0 + 8) * ASTRIDE + kc + lr + 4]);
            }
            uint32_t bf[8][2];
#pragma unroll
            for (int nt = 0; nt < 8; nt++) {
                int col = wn0 + nt * 8 + lq;
                bf[nt][0] = __float_as_uint(Bs[(kc + lr    ) * BSTRIDE + col]);
                bf[nt][1] = __float_as_uint(Bs[(kc + lr + 4) * BSTRIDE + col]);
            }
#pragma unroll
            for (int mt = 0; mt < 4; mt++)
#pragma unroll
                for (int nt = 0; nt < 8; nt++) {
                    float* c = acc[mt][nt];
                    asm volatile(
                        "mma.sync.aligned.m16n8k8.row.col.f32.tf32.tf32.f32 "
                        "{%0,%1,%2,%3}, {%4,%5,%6,%7}, {%8,%9}, {%0,%1,%2,%3};"
                        : "+f"(c[0]), "+f"(c[1]), "+f"(c[2]), "+f"(c[3])
                        : "r"(af[mt][0]), "r"(af[mt][1]),
                          "r"(af[mt][2]), "r"(af[mt][3]),
                          "r"(bf[nt][0]), "r"(bf[nt][1]));
                }
        }
        __syncthreads();
    }

    // Epilogue. c0,c1 -> (row, col..col+1); c2,c3 -> (row+8, same cols)
#pragma unroll
    for (int mt = 0; mt < 4; mt++) {
        int r0 = m0 + wm0 + mt * 16 + lq;
        int r1 = r0 + 8;
        if (mode == 1) {
            float d0 = (r0 < M) ? g_dis[r0] : 0.f;
            float d1 = (r1 < M) ? g_dis[r1] : 0.f;
#pragma unroll
            for (int nt = 0; nt < 8; nt++) {
                int col = wn0 + nt * 8 + 2 * lr;
                float* c = acc[mt][nt];
                if (r0 < M)
                    *(__half2*)(g_hw + (size_t)r0 * TBN + col) =
                        __floats2half2_rn(c[0] * d0, c[1] * d0);
                if (r1 < M)
                    *(__half2*)(g_hw + (size_t)r1 * TBN + col) =
                        __floats2half2_rn(c[2] * d1, c[3] * d1);
            }
        } else {
#pragma unroll
            for (int nt = 0; nt < 8; nt++) {
                int col = wn0 + nt * 8 + 2 * lr;
                float2 bv = *(const float2*)(bias + col);
                float* c = acc[mt][nt];
                if (r0 < M) {
                    float2 v = make_float2(c[0] + bv.x, c[1] + bv.y);
                    *(float2*)(g_h + (size_t)r0 * TBN + col) = v;
                }
                if (r1 < M) {
                    float2 v = make_float2(c[2] + bv.x, c[3] + bv.y);
                    *(float2*)(g_h + (size_t)r1 * TBN + col) = v;
                }
            }
        }
    }
}

// ---------------------------------------------------------------------------
// SIMT SGEMM (kept for lin1: Nc=128): tiled 128x128x16
// g_h1 = relu(C + bias), A = g_h
// ---------------------------------------------------------------------------
#define BM 128
#define BN 128
#define BKK 16

__global__ void __launch_bounds__(256)
k_gemm(const float* __restrict__ B, const float* __restrict__ bias,
       int M, int K, int Nc) {
    const float* __restrict__ A = g_h;

    __shared__ float As[BKK][BM + 4];
    __shared__ float Bs[BKK][BN + 4];

    const int m0 = blockIdx.x * BM;
    const int n0 = blockIdx.y * BN;
    const int tid = threadIdx.x;
    const int tr = tid >> 4;
    const int tc = tid & 15;

    float acc[8][8];
#pragma unroll
    for (int i = 0; i < 8; i++)
#pragma unroll
        for (int j = 0; j < 8; j++) acc[i][j] = 0.f;

    for (int k0 = 0; k0 < K; k0 += BKK) {
#pragma unroll
        for (int l = 0; l < 2; l++) {
            int f = tid * 2 + l;
            int row = f >> 2;
            int c4 = (f & 3) * 4;
            float4 v = make_float4(0.f, 0.f, 0.f, 0.f);
            int m = m0 + row;
            if (m < M) v = *(const float4*)(A + (size_t)m * K + k0 + c4);
            As[c4 + 0][row] = v.x;
            As[c4 + 1][row] = v.y;
            As[c4 + 2][row] = v.z;
            As[c4 + 3][row] = v.w;
        }
#pragma unroll
        for (int l = 0; l < 2; l++) {
            int f = tid * 2 + l;
            int row = f >> 5;
            int c4 = (f & 31) * 4;
            float4 v = *(const float4*)(B + (size_t)(k0 + row) * Nc + n0 + c4);
            *(float4*)&Bs[row][c4] = v;
        }
        __syncthreads();

#pragma unroll
        for (int k = 0; k < BKK; k++) {
            float ra[8], rb[8];
            *(float4*)(ra)     = *(const float4*)&As[k][tr * 8];
            *(float4*)(ra + 4) = *(const float4*)&As[k][tr * 8 + 4];
            *(float4*)(rb)     = *(const float4*)&Bs[k][tc * 8];
            *(float4*)(rb + 4) = *(const float4*)&Bs[k][tc * 8 + 4];
#pragma unroll
            for (int i = 0; i < 8; i++)
#pragma unroll
                for (int j = 0; j < 8; j++)
                    acc[i][j] += ra[i] * rb[j];
        }
        __syncthreads();
    }

    const int nbase = n0 + tc * 8;
    float bb[8];
#pragma unroll
    for (int j = 0; j < 8; j++) bb[j] = bias[nbase + j];

#pragma unroll
    for (int i = 0; i < 8; i++) {
        int m = m0 + tr * 8 + i;
        if (m >= M) break;
        size_t off = (size_t)m * Nc + nbase;
        float4 v0, v1;
        v0.x = fmaxf(acc[i][0] + bb[0], 0.f); v0.y = fmaxf(acc[i][1] + bb[1], 0.f);
        v0.z = fmaxf(acc[i][2] + bb[2], 0.f); v0.w = fmaxf(acc[i][3] + bb[3], 0.f);
        v1.x = fmaxf(acc[i][4] + bb[4], 0.f); v1.y = fmaxf(acc[i][5] + bb[5], 0.f);
        v1.z = fmaxf(acc[i][6] + bb[6], 0.f); v1.w = fmaxf(acc[i][7] + bb[7], 0.f);
        *(float4*)(g_h1 + off) = v0;
        *(float4*)(g_h1 + off + 4) = v1;
    }
}

// ---------------------------------------------------------------------------
// Fused aggregate + finish: warp per node, fp16 gather / fp32 accumulate.
// Each lane owns 8 contiguous columns (one uint4 = 8 halves per row).
//   acc = hw[node] + sum_{r in CSR row} hw[r]
//   h[node] = relu(LN(acc*dis + conv_b) * g + b)
// Neighbor loop unrolled x4 -> 4 outstanding 16B loads per lane.
// ---------------------------------------------------------------------------
__device__ __forceinline__ void acc_row(float* a, uint4 u) {
    const __half2* p = (const __half2*)&u;
#pragma unroll
    for (int i = 0; i < 4; i++) {
        float2 f = __half22float2(p[i]);
        a[2 * i]     += f.x;
        a[2 * i + 1] += f.y;
    }
}

__global__ void __launch_bounds__(256)
k_agg_finish(const float* __restrict__ cb, const float* __restrict__ lg,
             const float* __restrict__ lb, int n) {
    int node = (blockIdx.x * blockDim.x + threadIdx.x) >> 5;
    if (node >= n) return;
    int lane = threadIdx.x & 31;
    size_t base = (size_t)node * HID;

    float a[8];
#pragma unroll
    for (int i = 0; i < 8; i++) a[i] = 0.f;

    // self-loop
    acc_row(a, __ldg((const uint4*)(g_hw + base) + lane));

    int e   = g_rowptr[node];
    int end = g_rowptr[node + 1];

    for (; e + 3 < end; e += 4) {
        int r0 = __ldg(&g_csr[e]);
        int r1 = __ldg(&g_csr[e + 1]);
        int r2 = __ldg(&g_csr[e + 2]);
        int r3 = __ldg(&g_csr[e + 3]);
        uint4 u0 = __ldg((const uint4*)(g_hw + (size_t)r0 * HID) + lane);
        uint4 u1 = __ldg((const uint4*)(g_hw + (size_t)r1 * HID) + lane);
        uint4 u2 = __ldg((const uint4*)(g_hw + (size_t)r2 * HID) + lane);
        uint4 u3 = __ldg((const uint4*)(g_hw + (size_t)r3 * HID) + lane);
        acc_row(a, u0); acc_row(a, u1); acc_row(a, u2); acc_row(a, u3);
    }
    for (; e < end; e++) {
        int r0 = __ldg(&g_csr[e]);
        acc_row(a, __ldg((const uint4*)(g_hw + (size_t)r0 * HID) + lane));
    }

    // finish: v = a*dis + conv_b; LN; relu. Lane owns cols [lane*8, lane*8+8).
    float d = g_dis[node];
    float4 c0 = ((const float4*)cb)[lane * 2];
    float4 c1 = ((const float4*)cb)[lane * 2 + 1];

    float v[8];
    v[0] = a[0] * d + c0.x; v[1] = a[1] * d + c0.y;
    v[2] = a[2] * d + c0.z; v[3] = a[3] * d + c0.w;
    v[4] = a[4] * d + c1.x; v[5] = a[5] * d + c1.y;
    v[6] = a[6] * d + c1.z; v[7] = a[7] * d + c1.w;

    float s = 0.f, sq = 0.f;
#pragma unroll
    for (int i = 0; i < 8; i++) { s += v[i]; sq += v[i] * v[i]; }
#pragma unroll
    for (int o = 16; o > 0; o >>= 1) {
        s  += __shfl_xor_sync(0xffffffffu, s, o);
        sq += __shfl_xor_sync(0xffffffffu, sq, o);
    }
    float mu = s * (1.f / HID);
    float var = sq * (1.f / HID) - mu * mu;
    float rs = rsqrtf(var + LN_EPS);

    float4 g0 = ((const float4*)lg)[lane * 2];
    float4 g1 = ((const float4*)lg)[lane * 2 + 1];
    float4 b0 = ((const float4*)lb)[lane * 2];
    float4 b1 = ((const float4*)lb)[lane * 2 + 1];

    float4 o0, o1;
    o0.x = fmaxf((v[0] - mu) * rs * g0.x + b0.x, 0.f);
    o0.y = fmaxf((v[1] - mu) * rs * g0.y + b0.y, 0.f);
    o0.z = fmaxf((v[2] - mu) * rs * g0.z + b0.z, 0.f);
    o0.w = fmaxf((v[3] - mu) * rs * g0.w + b0.w, 0.f);
    o1.x = fmaxf((v[4] - mu) * rs * g1.x + b1.x, 0.f);
    o1.y = fmaxf((v[5] - mu) * rs * g1.y + b1.y, 0.f);
    o1.z = fmaxf((v[6] - mu) * rs * g1.z + b1.z, 0.f);
    o1.w = fmaxf((v[7] - mu) * rs * g1.w + b1.w, 0.f);

    *(float4*)(g_h + base + lane * 8) = o0;
    *(float4*)(g_h + base + lane * 8 + 4) = o1;
}

// ---------------------------------------------------------------------------
// lin2: out[n] = h1[n,:] . w + b, warp per node (128-dot)
// ---------------------------------------------------------------------------
__global__ void __launch_bounds__(256)
k_lin2(const float* __restrict__ w, const float* __restrict__ b,
       float* __restrict__ out, int n) {
    int node = (blockIdx.x * blockDim.x + threadIdx.x) >> 5;
    if (node >= n) return;
    int lane = threadIdx.x & 31;

    float4 h = *(const float4*)(g_h1 + (size_t)node * (HID / 2) + lane * 4);
    float4 wv = ((const float4*)w)[lane];
    float s = h.x * wv.x + h.y * wv.y + h.z * wv.z + h.w * wv.w;
#pragma unroll
    for (int o = 16; o > 0; o >>= 1)
        s += __shfl_xor_sync(0xffffffffu, s, o);
    if (lane == 0) out[node] = s + b[0];
}

// ---------------------------------------------------------------------------
// Launch
// ---------------------------------------------------------------------------
extern "C" void kernel_launch(void* const* d_in, const int* in_sizes, int n_in,
                              void* d_out, int out_size) {
    const float* x      = (const float*)d_in[0];
    const void*  ei     = d_in[1];                 // int32 or int64 — probed
    const float* enc_w  = (const float*)d_in[2];
    const float* enc_b  = (const float*)d_in[3];
    const float* conv_w = (const float*)d_in[4];
    const float* conv_b = (const float*)d_in[5];
    const float* ln_g   = (const float*)d_in[6];
    const float* ln_b   = (const float*)d_in[7];
    const float* lin1_w = (const float*)d_in[8];
    const float* lin1_b = (const float*)d_in[9];
    const float* lin2_w = (const float*)d_in[10];
    const float* lin2_b = (const float*)d_in[11];
    float* out = (float*)d_out;

    const int N = in_sizes[0] / IN_C;    // 100000
    const int E = in_sizes[1] / 2;       // 1600000

    int nsamp = (E >= 1024) ? 1024 : (E > 0 ? E : 1);
    k_detect<<<1, 256>>>((const long long*)ei, nsamp, N);

    // Degree + normalization + CSR (recomputed every call: deterministic)
    const int nblk = (N + 255) / 256;
    k_deg_init<<<nblk, 256>>>(N);
    k_deg_count<<<(E + 255) / 256, 256>>>(ei, E, N);
    k_dis<<<nblk, 256>>>(N);
    k_scan1<<<nblk, 256>>>(N);
    k_scan2<<<1, 1024>>>(nblk, N);
    k_scan3<<<nblk, 256>>>(N);
    k_fill<<<(E + 255) / 256, 256>>>(ei, E, N);

    const int tf32_blocks = (N + TBM - 1) / TBM;

    // Encoder: g_h = x @ enc_w + enc_b   (tf32, K=128)
    k_gemm_tf32<<<tf32_blocks, 256>>>(x, enc_w, enc_b, N, IN_C, 0);

    const int node_warp_blocks = (N * 32 + 255) / 256;

    for (int i = 0; i < NLAYERS; i++) {
        // hw = half((g_h @ W_i) * dis)   (tf32, K=256)
        k_gemm_tf32<<<tf32_blocks, 256>>>(nullptr,
                                          conv_w + (size_t)i * HID * HID,
                                          nullptr, N, HID, 1);
        // h = relu(LN((hw[node] + sum_neighbors hw)*dis + b))
        k_agg_finish<<<node_warp_blocks, 256>>>(conv_b + (size_t)i * HID,
                                                ln_g + (size_t)i * HID,
                                                ln_b + (size_t)i * HID, N);
    }

    // lin1 (+relu) SIMT, then lin2
    dim3 g_lin1((N + BM - 1) / BM, (HID / 2) / BN);
    k_gemm<<<g_lin1, 256>>>(lin1_w, lin1_b, N, HID, HID / 2);
    k_lin2<<<node_warp_blocks, 256>>>(lin2_w, lin2_b, out, N);
}

// round 14
// speedup vs baseline: 3.9141x; 1.2327x over previous
#include <cuda_runtime.h>
#include <cuda_fp16.h>
#include <cstdint>

// ---------------------------------------------------------------------------
// StressGCN: 4-layer GCN, N=100000 nodes, E=1.6M edges, IN_C=128, HID=256.
// h = relu(LN(agg(h@W)*dis + b)) x4, bracketed by encoder / lin1+relu / lin2.
// CSR gather aggregation; tf32 tensor-core GEMMs with cp.async double
// buffering; fp16 gather source (g_hw) with fp32 accumulation.
// ---------------------------------------------------------------------------

#define NNODES   100000
#define EMAX     1700000
#define IN_C     128
#define HID      256
#define NLAYERS  4
#define LN_EPS   1e-5f

// Scratch (device globals: allocation is forbidden)
__device__ float  g_h  [(size_t)NNODES * HID];      // current features
__device__ __half g_hw [(size_t)NNODES * HID];      // scaled h@W, fp16 (gather)
__device__ float  g_h1 [(size_t)NNODES * (HID/2)];  // lin1 output
__device__ float  g_dis[NNODES];
__device__ int    g_deg[NNODES];                    // 1 + in-degree
__device__ int    g_rowptr[NNODES + 1];
__device__ int    g_cursor[NNODES];
__device__ int    g_blocksum[1024];
__device__ int    g_csr[EMAX];                      // source node per edge slot
__device__ int    g_is32;                           // 1 if edge_index is int32

// ---------------------------------------------------------------------------
// Edge-index dtype probe (int64 vs int32 read as int64 -> out-of-range)
// ---------------------------------------------------------------------------
__global__ void k_detect(const long long* __restrict__ ei, int nsamp, int N) {
    __shared__ int bad;
    if (threadIdx.x == 0) bad = 0;
    __syncthreads();
    for (int i = threadIdx.x; i < nsamp; i += blockDim.x) {
        long long v = ei[i];
        if (v < 0 || v >= (long long)N) bad = 1;
    }
    __syncthreads();
    if (threadIdx.x == 0) g_is32 = bad;
}

__device__ __forceinline__ int edge_at(const void* ei, size_t pos, int is32) {
    return is32 ? ((const int*)ei)[pos]
                : (int)(((const long long*)ei)[pos]);
}

// ---------------------------------------------------------------------------
// Degree / normalization / CSR build
// ---------------------------------------------------------------------------
__global__ void k_deg_init(int n) {
    int i = blockIdx.x * blockDim.x + threadIdx.x;
    if (i < n) g_deg[i] = 1;  // self loop
}

__global__ void k_deg_count(const void* __restrict__ ei, int E, int N) {
    int e = blockIdx.x * blockDim.x + threadIdx.x;
    if (e >= E) return;
    int c = edge_at(ei, (size_t)E + e, g_is32);   // target
    if ((unsigned)c < (unsigned)N)
        atomicAdd(&g_deg[c], 1);
}

__global__ void k_dis(int n) {
    int i = blockIdx.x * blockDim.x + threadIdx.x;
    if (i < n) g_dis[i] = rsqrtf((float)g_deg[i]);
}

// Exclusive scan of (deg-1) [edge-only degree], 3-pass block scan.
__global__ void k_scan1(int n) {
    __shared__ int s[256];
    int idx = blockIdx.x * 256 + threadIdx.x;
    int v = (idx < n) ? (g_deg[idx] - 1) : 0;
    s[threadIdx.x] = v;
    __syncthreads();
#pragma unroll
    for (int off = 1; off < 256; off <<= 1) {
        int t = (threadIdx.x >= off) ? s[threadIdx.x - off] : 0;
        __syncthreads();
        s[threadIdx.x] += t;
        __syncthreads();
    }
    if (idx < n) g_rowptr[idx] = s[threadIdx.x] - v;   // exclusive
    if (threadIdx.x == 255) g_blocksum[blockIdx.x] = s[255];
}

__global__ void k_scan2(int nb, int N) {
    __shared__ int s[1024];
    int tid = threadIdx.x;
    int v = (tid < nb) ? g_blocksum[tid] : 0;
    s[tid] = v;
    __syncthreads();
#pragma unroll
    for (int off = 1; off < 1024; off <<= 1) {
        int t = (tid >= off) ? s[tid - off] : 0;
        __syncthreads();
        s[tid] += t;
        __syncthreads();
    }
    if (tid < nb) g_blocksum[tid] = s[tid] - v;        // exclusive
    if (tid == nb - 1) g_rowptr[N] = s[tid];           // total edge count
}

__global__ void k_scan3(int n) {
    int idx = blockIdx.x * blockDim.x + threadIdx.x;
    if (idx < n) {
        int r = g_rowptr[idx] + g_blocksum[blockIdx.x];
        g_rowptr[idx] = r;
        g_cursor[idx] = r;
    }
}

__global__ void k_fill(const void* __restrict__ ei, int E, int N) {
    int e = blockIdx.x * blockDim.x + threadIdx.x;
    if (e >= E) return;
    int is32 = g_is32;
    int r = edge_at(ei, e, is32);
    int c = edge_at(ei, (size_t)E + e, is32);
    if ((unsigned)r >= (unsigned)N || (unsigned)c >= (unsigned)N) return;
    int pos = atomicAdd(&g_cursor[c], 1);
    if (pos < EMAX) g_csr[pos] = r;
}

// ---------------------------------------------------------------------------
// TF32 tensor-core GEMM, cp.async double-buffered.
// C[M,TBN_] = A[M,K] @ B[K,TBN_]; block tile 128 x TBN_ x 32, 256 threads =
// 8 warps (2m x 4n); warp tile 64 x (TBN_/4); mma.m16n8k8 fragments.
// mode 0: g_h  = C + bias          (encoder, TBN_=256)
// mode 1: g_hw = half(C * dis[m])  (conv pre-scale; A = g_h, TBN_=256)
// mode 2: g_h1 = relu(C + bias)    (lin1; A = g_h, TBN_=128)
// ---------------------------------------------------------------------------
#define TBM 128
#define TBK 32
#define ASTRIDE 36   // 32 + 4: fragment LDS conflict-free, float4-aligned

__device__ __forceinline__ void cp16(float* smem, const float* g, bool pred) {
    uint32_t s = (uint32_t)__cvta_generic_to_shared(smem);
    int sz = pred ? 16 : 0;
    asm volatile("cp.async.cg.shared.global [%0], [%1], 16, %2;"
                 :: "r"(s), "l"(g), "r"(sz));
}

template <int TBN_>
__device__ __forceinline__ void load_tiles_async(
    float* __restrict__ as, float* __restrict__ bs,
    const float* __restrict__ A, const float* __restrict__ B,
    int m0, int k0, int M, int K, int tid)
{
    constexpr int BSTRIDE_ = TBN_ + 8;
    // A tile: 128x32 floats = 1024 float4; 4 per thread
#pragma unroll
    for (int i = 0; i < 4; i++) {
        int f = i * 256 + tid;
        int row = f >> 3;
        int c4 = (f & 7) * 4;
        int m = m0 + row;
        cp16(&as[row * ASTRIDE + c4], A + (size_t)m * K + k0 + c4, m < M);
    }
    // B tile: 32 x TBN_ floats; TBN_/32 float4 per thread
#pragma unroll
    for (int i = 0; i < TBN_ / 32; i++) {
        int f = i * 256 + tid;
        int row = f / (TBN_ / 4);
        int c4 = (f % (TBN_ / 4)) * 4;
        cp16(&bs[row * BSTRIDE_ + c4], B + (size_t)(k0 + row) * TBN_ + c4, true);
    }
}

template <int TBN_>
__global__ void __launch_bounds__(256, 1)
k_gemm_tf32(const float* __restrict__ Aext, const float* __restrict__ B,
            const float* __restrict__ bias, int M, int K, int mode) {
    constexpr int BSTRIDE_ = TBN_ + 8;
    constexpr int NT = TBN_ / 32;          // n-fragments per warp
    const float* __restrict__ A = Aext ? Aext : g_h;

    __shared__ float As[2][TBM * ASTRIDE];
    __shared__ float Bs[2][TBK * BSTRIDE_];

    const int tid  = threadIdx.x;
    const int lane = tid & 31;
    const int wid  = tid >> 5;
    const int wm0  = (wid & 1) * 64;              // warp m-origin in tile
    const int wn0  = (wid >> 1) * (TBN_ / 4);     // warp n-origin in tile
    const int m0   = blockIdx.x * TBM;

    const int lq = lane >> 2;             // 0..7
    const int lr = lane & 3;              // 0..3

    float acc[4][NT][4];
#pragma unroll
    for (int mt = 0; mt < 4; mt++)
#pragma unroll
        for (int nt = 0; nt < NT; nt++)
#pragma unroll
            for (int i = 0; i < 4; i++) acc[mt][nt][i] = 0.f;

    const int NIT = K / TBK;

    load_tiles_async<TBN_>(As[0], Bs[0], A, B, m0, 0, M, K, tid);
    asm volatile("cp.async.commit_group;" ::: "memory");

    for (int it = 0; it < NIT; it++) {
        asm volatile("cp.async.wait_group 0;" ::: "memory");
        __syncthreads();
        if (it + 1 < NIT) {
            load_tiles_async<TBN_>(As[(it + 1) & 1], Bs[(it + 1) & 1],
                                   A, B, m0, (it + 1) * TBK, M, K, tid);
            asm volatile("cp.async.commit_group;" ::: "memory");
        }
        const float* __restrict__ as = As[it & 1];
        const float* __restrict__ bs = Bs[it & 1];

#pragma unroll
        for (int ks = 0; ks < 4; ks++) {
            const int kc = ks * 8;
            uint32_t af[4][4];
#pragma unroll
            for (int mt = 0; mt < 4; mt++) {
                int r0 = wm0 + mt * 16 + lq;
                af[mt][0] = __float_as_uint(as[(r0    ) * ASTRIDE + kc + lr    ]);
                af[mt][1] = __float_as_uint(as[(r0 + 8) * ASTRIDE + kc + lr    ]);
                af[mt][2] = __float_as_uint(as[(r0    ) * ASTRIDE + kc + lr + 4]);
                af[mt][3] = __float_as_uint(as[(r0 + 8) * ASTRIDE + kc + lr + 4]);
            }
            uint32_t bf[NT][2];
#pragma unroll
            for (int nt = 0; nt < NT; nt++) {
                int col = wn0 + nt * 8 + lq;
                bf[nt][0] = __float_as_uint(bs[(kc + lr    ) * BSTRIDE_ + col]);
                bf[nt][1] = __float_as_uint(bs[(kc + lr + 4) * BSTRIDE_ + col]);
            }
#pragma unroll
            for (int mt = 0; mt < 4; mt++)
#pragma unroll
                for (int nt = 0; nt < NT; nt++) {
                    float* c = acc[mt][nt];
                    asm volatile(
                        "mma.sync.aligned.m16n8k8.row.col.f32.tf32.tf32.f32 "
                        "{%0,%1,%2,%3}, {%4,%5,%6,%7}, {%8,%9}, {%0,%1,%2,%3};"
                        : "+f"(c[0]), "+f"(c[1]), "+f"(c[2]), "+f"(c[3])
                        : "r"(af[mt][0]), "r"(af[mt][1]),
                          "r"(af[mt][2]), "r"(af[mt][3]),
                          "r"(bf[nt][0]), "r"(bf[nt][1]));
                }
        }
        __syncthreads();
    }

    // Epilogue. c0,c1 -> (row, col..col+1); c2,c3 -> (row+8, same cols)
#pragma unroll
    for (int mt = 0; mt < 4; mt++) {
        int r0 = m0 + wm0 + mt * 16 + lq;
        int r1 = r0 + 8;
        if (mode == 1) {
            float d0 = (r0 < M) ? g_dis[r0] : 0.f;
            float d1 = (r1 < M) ? g_dis[r1] : 0.f;
#pragma unroll
            for (int nt = 0; nt < NT; nt++) {
                int col = wn0 + nt * 8 + 2 * lr;
                float* c = acc[mt][nt];
                if (r0 < M)
                    *(__half2*)(g_hw + (size_t)r0 * TBN_ + col) =
                        __floats2half2_rn(c[0] * d0, c[1] * d0);
                if (r1 < M)
                    *(__half2*)(g_hw + (size_t)r1 * TBN_ + col) =
                        __floats2half2_rn(c[2] * d1, c[3] * d1);
            }
        } else if (mode == 0) {
#pragma unroll
            for (int nt = 0; nt < NT; nt++) {
                int col = wn0 + nt * 8 + 2 * lr;
                float2 bv = *(const float2*)(bias + col);
                float* c = acc[mt][nt];
                if (r0 < M) {
                    float2 v = make_float2(c[0] + bv.x, c[1] + bv.y);
                    *(float2*)(g_h + (size_t)r0 * TBN_ + col) = v;
                }
                if (r1 < M) {
                    float2 v = make_float2(c[2] + bv.x, c[3] + bv.y);
                    *(float2*)(g_h + (size_t)r1 * TBN_ + col) = v;
                }
            }
        } else {  // mode 2: relu + bias -> g_h1
#pragma unroll
            for (int nt = 0; nt < NT; nt++) {
                int col = wn0 + nt * 8 + 2 * lr;
                float2 bv = *(const float2*)(bias + col);
                float* c = acc[mt][nt];
                if (r0 < M) {
                    float2 v = make_float2(fmaxf(c[0] + bv.x, 0.f),
                                           fmaxf(c[1] + bv.y, 0.f));
                    *(float2*)(g_h1 + (size_t)r0 * TBN_ + col) = v;
                }
                if (r1 < M) {
                    float2 v = make_float2(fmaxf(c[2] + bv.x, 0.f),
                                           fmaxf(c[3] + bv.y, 0.f));
                    *(float2*)(g_h1 + (size_t)r1 * TBN_ + col) = v;
                }
            }
        }
    }
}

// ---------------------------------------------------------------------------
// Fused aggregate + finish: warp per node, fp16 gather / fp32 accumulate.
// Each lane owns 8 contiguous columns (one uint4 = 8 halves per row).
//   acc = hw[node] + sum_{r in CSR row} hw[r]
//   h[node] = relu(LN(acc*dis + conv_b) * g + b)
// Neighbor loop unrolled x4 -> 4 outstanding 16B loads per lane.
// ---------------------------------------------------------------------------
__device__ __forceinline__ void acc_row(float* a, uint4 u) {
    const __half2* p = (const __half2*)&u;
#pragma unroll
    for (int i = 0; i < 4; i++) {
        float2 f = __half22float2(p[i]);
        a[2 * i]     += f.x;
        a[2 * i + 1] += f.y;
    }
}

__global__ void __launch_bounds__(256)
k_agg_finish(const float* __restrict__ cb, const float* __restrict__ lg,
             const float* __restrict__ lb, int n) {
    int node = (blockIdx.x * blockDim.x + threadIdx.x) >> 5;
    if (node >= n) return;
    int lane = threadIdx.x & 31;
    size_t base = (size_t)node * HID;

    float a[8];
#pragma unroll
    for (int i = 0; i < 8; i++) a[i] = 0.f;

    // self-loop
    acc_row(a, __ldg((const uint4*)(g_hw + base) + lane));

    int e   = g_rowptr[node];
    int end = g_rowptr[node + 1];

    for (; e + 3 < end; e += 4) {
        int r0 = __ldg(&g_csr[e]);
        int r1 = __ldg(&g_csr[e + 1]);
        int r2 = __ldg(&g_csr[e + 2]);
        int r3 = __ldg(&g_csr[e + 3]);
        uint4 u0 = __ldg((const uint4*)(g_hw + (size_t)r0 * HID) + lane);
        uint4 u1 = __ldg((const uint4*)(g_hw + (size_t)r1 * HID) + lane);
        uint4 u2 = __ldg((const uint4*)(g_hw + (size_t)r2 * HID) + lane);
        uint4 u3 = __ldg((const uint4*)(g_hw + (size_t)r3 * HID) + lane);
        acc_row(a, u0); acc_row(a, u1); acc_row(a, u2); acc_row(a, u3);
    }
    for (; e < end; e++) {
        int r0 = __ldg(&g_csr[e]);
        acc_row(a, __ldg((const uint4*)(g_hw + (size_t)r0 * HID) + lane));
    }

    // finish: v = a*dis + conv_b; LN; relu. Lane owns cols [lane*8, lane*8+8).
    float d = g_dis[node];
    float4 c0 = ((const float4*)cb)[lane * 2];
    float4 c1 = ((const float4*)cb)[lane * 2 + 1];

    float v[8];
    v[0] = a[0] * d + c0.x; v[1] = a[1] * d + c0.y;
    v[2] = a[2] * d + c0.z; v[3] = a[3] * d + c0.w;
    v[4] = a[4] * d + c1.x; v[5] = a[5] * d + c1.y;
    v[6] = a[6] * d + c1.z; v[7] = a[7] * d + c1.w;

    float s = 0.f, sq = 0.f;
#pragma unroll
    for (int i = 0; i < 8; i++) { s += v[i]; sq += v[i] * v[i]; }
#pragma unroll
    for (int o = 16; o > 0; o >>= 1) {
        s  += __shfl_xor_sync(0xffffffffu, s, o);
        sq += __shfl_xor_sync(0xffffffffu, sq, o);
    }
    float mu = s * (1.f / HID);
    float var = sq * (1.f / HID) - mu * mu;
    float rs = rsqrtf(var + LN_EPS);

    float4 g0 = ((const float4*)lg)[lane * 2];
    float4 g1 = ((const float4*)lg)[lane * 2 + 1];
    float4 b0 = ((const float4*)lb)[lane * 2];
    float4 b1 = ((const float4*)lb)[lane * 2 + 1];

    float4 o0, o1;
    o0.x = fmaxf((v[0] - mu) * rs * g0.x + b0.x, 0.f);
    o0.y = fmaxf((v[1] - mu) * rs * g0.y + b0.y, 0.f);
    o0.z = fmaxf((v[2] - mu) * rs * g0.z + b0.z, 0.f);
    o0.w = fmaxf((v[3] - mu) * rs * g0.w + b0.w, 0.f);
    o1.x = fmaxf((v[4] - mu) * rs * g1.x + b1.x, 0.f);
    o1.y = fmaxf((v[5] - mu) * rs * g1.y + b1.y, 0.f);
    o1.z = fmaxf((v[6] - mu) * rs * g1.z + b1.z, 0.f);
    o1.w = fmaxf((v[7] - mu) * rs * g1.w + b1.w, 0.f);

    *(float4*)(g_h + base + lane * 8) = o0;
    *(float4*)(g_h + base + lane * 8 + 4) = o1;
}

// ---------------------------------------------------------------------------
// lin2: out[n] = h1[n,:] . w + b, warp per node (128-dot)
// ---------------------------------------------------------------------------
__global__ void __launch_bounds__(256)
k_lin2(const float* __restrict__ w, const float* __restrict__ b,
       float* __restrict__ out, int n) {
    int node = (blockIdx.x * blockDim.x + threadIdx.x) >> 5;
    if (node >= n) return;
    int lane = threadIdx.x & 31;

    float4 h = *(const float4*)(g_h1 + (size_t)node * (HID / 2) + lane * 4);
    float4 wv = ((const float4*)w)[lane];
    float s = h.x * wv.x + h.y * wv.y + h.z * wv.z + h.w * wv.w;
#pragma unroll
    for (int o = 16; o > 0; o >>= 1)
        s += __shfl_xor_sync(0xffffffffu, s, o);
    if (lane == 0) out[node] = s + b[0];
}

// ---------------------------------------------------------------------------
// Launch
// ---------------------------------------------------------------------------
extern "C" void kernel_launch(void* const* d_in, const int* in_sizes, int n_in,
                              void* d_out, int out_size) {
    const float* x      = (const float*)d_in[0];
    const void*  ei     = d_in[1];                 // int32 or int64 — probed
    const float* enc_w  = (const float*)d_in[2];
    const float* enc_b  = (const float*)d_in[3];
    const float* conv_w = (const float*)d_in[4];
    const float* conv_b = (const float*)d_in[5];
    const float* ln_g   = (const float*)d_in[6];
    const float* ln_b   = (const float*)d_in[7];
    const float* lin1_w = (const float*)d_in[8];
    const float* lin1_b = (const float*)d_in[9];
    const float* lin2_w = (const float*)d_in[10];
    const float* lin2_b = (const float*)d_in[11];
    float* out = (float*)d_out;

    const int N = in_sizes[0] / IN_C;    // 100000
    const int E = in_sizes[1] / 2;       // 1600000

    int nsamp = (E >= 1024) ? 1024 : (E > 0 ? E : 1);
    k_detect<<<1, 256>>>((const long long*)ei, nsamp, N);

    // Degree + normalization + CSR (recomputed every call: deterministic)
    const int nblk = (N + 255) / 256;
    k_deg_init<<<nblk, 256>>>(N);
    k_deg_count<<<(E + 255) / 256, 256>>>(ei, E, N);
    k_dis<<<nblk, 256>>>(N);
    k_scan1<<<nblk, 256>>>(N);
    k_scan2<<<1, 1024>>>(nblk, N);
    k_scan3<<<nblk, 256>>>(N);
    k_fill<<<(E + 255) / 256, 256>>>(ei, E, N);

    const int tf32_blocks = (N + TBM - 1) / TBM;

    // Encoder: g_h = x @ enc_w + enc_b   (tf32, K=128)
    k_gemm_tf32<256><<<tf32_blocks, 256>>>(x, enc_w, enc_b, N, IN_C, 0);

    const int node_warp_blocks = (N * 32 + 255) / 256;

    for (int i = 0; i < NLAYERS; i++) {
        // hw = half((g_h @ W_i) * dis)   (tf32, K=256)
        k_gemm_tf32<256><<<tf32_blocks, 256>>>(nullptr,
                                               conv_w + (size_t)i * HID * HID,
                                               nullptr, N, HID, 1);
        // h = relu(LN((hw[node] + sum_neighbors hw)*dis + b))
        k_agg_finish<<<node_warp_blocks, 256>>>(conv_b + (size_t)i * HID,
                                                ln_g + (size_t)i * HID,
                                                ln_b + (size_t)i * HID, N);
    }

    // lin1 (+relu) on tensor cores (TBN=128), then lin2
    k_gemm_tf32<128><<<tf32_blocks, 256>>>(nullptr, lin1_w, lin1_b,
                                           N, HID, 2);
    k_lin2<<<node_warp_blocks, 256>>>(lin2_w, lin2_b, out, N);
}

// round 16
// speedup vs baseline: 4.3884x; 1.1212x over previous
#include <cuda_runtime.h>
#include <cuda_fp16.h>
#include <cstdint>

// ---------------------------------------------------------------------------
// StressGCN: 4-layer GCN, N=100000 nodes, E=1.6M edges, IN_C=128, HID=256.
// h = relu(LN(agg(h@W)*dis + b)) x4, bracketed by encoder / lin1+relu / lin2.
// CSR gather aggregation. Encoder: tf32 mma. Conv GEMMs: fp16 mma (m16n8k16,
// fp32 accum) on fp16 activations. lin1: 3xTF32 split-precision (no LN after
// it to wash error). All GEMMs cp.async double-buffered.
// NOTE: device globals (g_*) are referenced ONLY from device code — taking
// their address in host code yields the host shadow symbol (R15 bug: GB300
// ATS silently reads zero-filled host memory instead of faulting).
// ---------------------------------------------------------------------------

#define NNODES   100000
#define EMAX     1700000
#define IN_C     128
#define HID      256
#define NLAYERS  4
#define LN_EPS   1e-5f

// Scratch (device globals: allocation is forbidden)
__device__ float  g_h  [(size_t)NNODES * HID];      // fp32 h (last layer only)
__device__ __half g_hf [(size_t)NNODES * HID];      // fp16 h (conv A operand)
__device__ __half g_hw [(size_t)NNODES * HID];      // scaled h@W, fp16 (gather)
__device__ float  g_h1 [(size_t)NNODES * (HID/2)];  // lin1 output
__device__ __half g_wt [(size_t)NLAYERS * HID * HID]; // conv_w transposed fp16
__device__ float  g_dis[NNODES];
__device__ int    g_deg[NNODES];                    // 1 + in-degree
__device__ int    g_rowptr[NNODES + 1];
__device__ int    g_cursor[NNODES];
__device__ int    g_blocksum[1024];
__device__ int    g_csr[EMAX];                      // source node per edge slot
__device__ int    g_is32;                           // 1 if edge_index is int32

// ---------------------------------------------------------------------------
// Edge-index dtype probe (int64 vs int32 read as int64 -> out-of-range)
// ---------------------------------------------------------------------------
__global__ void k_detect(const long long* __restrict__ ei, int nsamp, int N) {
    __shared__ int bad;
    if (threadIdx.x == 0) bad = 0;
    __syncthreads();
    for (int i = threadIdx.x; i < nsamp; i += blockDim.x) {
        long long v = ei[i];
        if (v < 0 || v >= (long long)N) bad = 1;
    }
    __syncthreads();
    if (threadIdx.x == 0) g_is32 = bad;
}

__device__ __forceinline__ int edge_at(const void* ei, size_t pos, int is32) {
    return is32 ? ((const int*)ei)[pos]
                : (int)(((const long long*)ei)[pos]);
}

// ---------------------------------------------------------------------------
// Degree / normalization / CSR build
// ---------------------------------------------------------------------------
__global__ void k_deg_init(int n) {
    int i = blockIdx.x * blockDim.x + threadIdx.x;
    if (i < n) g_deg[i] = 1;  // self loop
}

__global__ void k_deg_count(const void* __restrict__ ei, int E, int N) {
    int e = blockIdx.x * blockDim.x + threadIdx.x;
    if (e >= E) return;
    int c = edge_at(ei, (size_t)E + e, g_is32);   // target
    if ((unsigned)c < (unsigned)N)
        atomicAdd(&g_deg[c], 1);
}

__global__ void k_dis(int n) {
    int i = blockIdx.x * blockDim.x + threadIdx.x;
    if (i < n) g_dis[i] = rsqrtf((float)g_deg[i]);
}

// Exclusive scan of (deg-1) [edge-only degree], 3-pass block scan.
__global__ void k_scan1(int n) {
    __shared__ int s[256];
    int idx = blockIdx.x * 256 + threadIdx.x;
    int v = (idx < n) ? (g_deg[idx] - 1) : 0;
    s[threadIdx.x] = v;
    __syncthreads();
#pragma unroll
    for (int off = 1; off < 256; off <<= 1) {
        int t = (threadIdx.x >= off) ? s[threadIdx.x - off] : 0;
        __syncthreads();
        s[threadIdx.x] += t;
        __syncthreads();
    }
    if (idx < n) g_rowptr[idx] = s[threadIdx.x] - v;   // exclusive
    if (threadIdx.x == 255) g_blocksum[blockIdx.x] = s[255];
}

__global__ void k_scan2(int nb, int N) {
    __shared__ int s[1024];
    int tid = threadIdx.x;
    int v = (tid < nb) ? g_blocksum[tid] : 0;
    s[tid] = v;
    __syncthreads();
#pragma unroll
    for (int off = 1; off < 1024; off <<= 1) {
        int t = (tid >= off) ? s[tid - off] : 0;
        __syncthreads();
        s[tid] += t;
        __syncthreads();
    }
    if (tid < nb) g_blocksum[tid] = s[tid] - v;        // exclusive
    if (tid == nb - 1) g_rowptr[N] = s[tid];           // total edge count
}

__global__ void k_scan3(int n) {
    int idx = blockIdx.x * blockDim.x + threadIdx.x;
    if (idx < n) {
        int r = g_rowptr[idx] + g_blocksum[blockIdx.x];
        g_rowptr[idx] = r;
        g_cursor[idx] = r;
    }
}

__global__ void k_fill(const void* __restrict__ ei, int E, int N) {
    int e = blockIdx.x * blockDim.x + threadIdx.x;
    if (e >= E) return;
    int is32 = g_is32;
    int r = edge_at(ei, e, is32);
    int c = edge_at(ei, (size_t)E + e, is32);
    if ((unsigned)r >= (unsigned)N || (unsigned)c >= (unsigned)N) return;
    int pos = atomicAdd(&g_cursor[c], 1);
    if (pos < EMAX) g_csr[pos] = r;
}

// Transpose + fp16-convert conv weights: g_wt[l][n][k] = conv_w[l][k][n]
__global__ void k_wt_convert(const float* __restrict__ w) {
    int idx = blockIdx.x * blockDim.x + threadIdx.x;  // L*HID*HID threads
    int l = idx >> 16;
    int k = (idx >> 8) & 255;
    int n = idx & 255;
    g_wt[((size_t)l * HID + n) * HID + k] = __float2half(w[idx]);
}

// ---------------------------------------------------------------------------
// cp.async helper (16B, zero-fill when !pred)
// ---------------------------------------------------------------------------
__device__ __forceinline__ void cp16(void* smem, const void* g, bool pred) {
    uint32_t s = (uint32_t)__cvta_generic_to_shared(smem);
    int sz = pred ? 16 : 0;
    asm volatile("cp.async.cg.shared.global [%0], [%1], 16, %2;"
                 :: "r"(s), "l"(g), "r"(sz));
}

// ---------------------------------------------------------------------------
// TF32 tensor-core GEMM, cp.async double-buffered.
// C[M,TBN_] = A[M,K] @ B[K,TBN_]; 256 threads = 8 warps (2m x 4n).
// mode 0: g_hf = half(C + bias)   (encoder, TBN_=256, A=x fp32)
// mode 2: g_h1 = relu(C + bias)   (lin1, TBN_=128, A=g_h fp32)
// SPLIT: 3xTF32 precision recovery (hi/lo operand split) — used by lin1,
// whose output is NOT followed by LayerNorm.
// ---------------------------------------------------------------------------
#define TBM 128
#define TBK 32
#define ASTRIDE 36   // fragment LDS conflict-free, float4-aligned

template <int TBN_>
__device__ __forceinline__ void load_tiles_async(
    float* __restrict__ as, float* __restrict__ bs,
    const float* __restrict__ A, const float* __restrict__ B,
    int m0, int k0, int M, int K, int tid)
{
    constexpr int BSTRIDE_ = TBN_ + 8;
#pragma unroll
    for (int i = 0; i < 4; i++) {
        int f = i * 256 + tid;
        int row = f >> 3;
        int c4 = (f & 7) * 4;
        int m = m0 + row;
        cp16(&as[row * ASTRIDE + c4], A + (size_t)m * K + k0 + c4, m < M);
    }
#pragma unroll
    for (int i = 0; i < TBN_ / 32; i++) {
        int f = i * 256 + tid;
        int row = f / (TBN_ / 4);
        int c4 = (f % (TBN_ / 4)) * 4;
        cp16(&bs[row * BSTRIDE_ + c4], B + (size_t)(k0 + row) * TBN_ + c4, true);
    }
}

__device__ __forceinline__ void mma_tf32(float* c, const uint32_t* a,
                                         const uint32_t* b) {
    asm volatile(
        "mma.sync.aligned.m16n8k8.row.col.f32.tf32.tf32.f32 "
        "{%0,%1,%2,%3}, {%4,%5,%6,%7}, {%8,%9}, {%0,%1,%2,%3};"
        : "+f"(c[0]), "+f"(c[1]), "+f"(c[2]), "+f"(c[3])
        : "r"(a[0]), "r"(a[1]), "r"(a[2]), "r"(a[3]), "r"(b[0]), "r"(b[1]));
}

template <int TBN_, bool SPLIT>
__global__ void __launch_bounds__(256, 1)
k_gemm_tf32(const float* __restrict__ Aext, const float* __restrict__ B,
            const float* __restrict__ bias, int M, int K, int mode) {
    constexpr int BSTRIDE_ = TBN_ + 8;
    constexpr int NT = TBN_ / 32;
    const float* __restrict__ A = Aext ? Aext : g_h;

    __shared__ float As[2][TBM * ASTRIDE];
    __shared__ float Bs[2][TBK * BSTRIDE_];

    const int tid  = threadIdx.x;
    const int lane = tid & 31;
    const int wid  = tid >> 5;
    const int wm0  = (wid & 1) * 64;
    const int wn0  = (wid >> 1) * (TBN_ / 4);
    const int m0   = blockIdx.x * TBM;

    const int lq = lane >> 2;
    const int lr = lane & 3;

    float acc[4][NT][4];
#pragma unroll
    for (int mt = 0; mt < 4; mt++)
#pragma unroll
        for (int nt = 0; nt < NT; nt++)
#pragma unroll
            for (int i = 0; i < 4; i++) acc[mt][nt][i] = 0.f;

    const int NIT = K / TBK;

    load_tiles_async<TBN_>(As[0], Bs[0], A, B, m0, 0, M, K, tid);
    asm volatile("cp.async.commit_group;" ::: "memory");

    for (int it = 0; it < NIT; it++) {
        asm volatile("cp.async.wait_group 0;" ::: "memory");
        __syncthreads();
        if (it + 1 < NIT) {
            load_tiles_async<TBN_>(As[(it + 1) & 1], Bs[(it + 1) & 1],
                                   A, B, m0, (it + 1) * TBK, M, K, tid);
            asm volatile("cp.async.commit_group;" ::: "memory");
        }
        const float* __restrict__ as = As[it & 1];
        const float* __restrict__ bs = Bs[it & 1];

#pragma unroll
        for (int ks = 0; ks < 4; ks++) {
            const int kc = ks * 8;
            uint32_t af[4][4];
#pragma unroll
            for (int mt = 0; mt < 4; mt++) {
                int r0 = wm0 + mt * 16 + lq;
                af[mt][0] = __float_as_uint(as[(r0    ) * ASTRIDE + kc + lr    ]);
                af[mt][1] = __float_as_uint(as[(r0 + 8) * ASTRIDE + kc + lr    ]);
                af[mt][2] = __float_as_uint(as[(r0    ) * ASTRIDE + kc + lr + 4]);
                af[mt][3] = __float_as_uint(as[(r0 + 8) * ASTRIDE + kc + lr + 4]);
            }
            uint32_t bf[NT][2];
#pragma unroll
            for (int nt = 0; nt < NT; nt++) {
                int col = wn0 + nt * 8 + lq;
                bf[nt][0] = __float_as_uint(bs[(kc + lr    ) * BSTRIDE_ + col]);
                bf[nt][1] = __float_as_uint(bs[(kc + lr + 4) * BSTRIDE_ + col]);
            }
            if (!SPLIT) {
#pragma unroll
                for (int mt = 0; mt < 4; mt++)
#pragma unroll
                    for (int nt = 0; nt < NT; nt++)
                        mma_tf32(acc[mt][nt], af[mt], bf[nt]);
            } else {
                // 3xTF32: a = hi + lo (hi tf32-exact), likewise b.
                uint32_t ah[4][4], al[4][4], bh[NT][2], bl[NT][2];
#pragma unroll
                for (int mt = 0; mt < 4; mt++)
#pragma unroll
                    for (int i = 0; i < 4; i++) {
                        uint32_t h = af[mt][i] & 0xffffe000u;
                        ah[mt][i] = h;
                        al[mt][i] = __float_as_uint(
                            __uint_as_float(af[mt][i]) - __uint_as_float(h));
                    }
#pragma unroll
                for (int nt = 0; nt < NT; nt++)
#pragma unroll
                    for (int i = 0; i < 2; i++) {
                        uint32_t h = bf[nt][i] & 0xffffe000u;
                        bh[nt][i] = h;
                        bl[nt][i] = __float_as_uint(
                            __uint_as_float(bf[nt][i]) - __uint_as_float(h));
                    }
#pragma unroll
                for (int mt = 0; mt < 4; mt++)
#pragma unroll
                    for (int nt = 0; nt < NT; nt++) {
                        mma_tf32(acc[mt][nt], al[mt], bh[nt]);
                        mma_tf32(acc[mt][nt], ah[mt], bl[nt]);
                        mma_tf32(acc[mt][nt], ah[mt], bh[nt]);
                    }
            }
        }
        __syncthreads();
    }

#pragma unroll
    for (int mt = 0; mt < 4; mt++) {
        int r0 = m0 + wm0 + mt * 16 + lq;
        int r1 = r0 + 8;
#pragma unroll
        for (int nt = 0; nt < NT; nt++) {
            int col = wn0 + nt * 8 + 2 * lr;
            float2 bv = *(const float2*)(bias + col);
            float* c = acc[mt][nt];
            if (mode == 0) {          // encoder -> fp16 g_hf
                if (r0 < M)
                    *(__half2*)(g_hf + (size_t)r0 * TBN_ + col) =
                        __floats2half2_rn(c[0] + bv.x, c[1] + bv.y);
                if (r1 < M)
                    *(__half2*)(g_hf + (size_t)r1 * TBN_ + col) =
                        __floats2half2_rn(c[2] + bv.x, c[3] + bv.y);
            } else {                  // lin1 -> relu fp32 g_h1
                if (r0 < M) {
                    float2 v = make_float2(fmaxf(c[0] + bv.x, 0.f),
                                           fmaxf(c[1] + bv.y, 0.f));
                    *(float2*)(g_h1 + (size_t)r0 * TBN_ + col) = v;
                }
                if (r1 < M) {
                    float2 v = make_float2(fmaxf(c[2] + bv.x, 0.f),
                                           fmaxf(c[3] + bv.y, 0.f));
                    *(float2*)(g_h1 + (size_t)r1 * TBN_ + col) = v;
                }
            }
        }
    }
}

// ---------------------------------------------------------------------------
// FP16 conv GEMM: g_hw = half((g_hf @ Wt^T) * dis), mma.m16n8k16 fp32-accum.
// Block tile 128x256x32(half), double-buffered cp.async. B from g_wt [n][k],
// selected by LAYER INDEX (device-side pointer arithmetic — see header note).
// ---------------------------------------------------------------------------
#define AST2 40
#define BST2 40

__device__ __forceinline__ void conv_load_async(
    __half* __restrict__ as, __half* __restrict__ bs,
    const __half* __restrict__ wt, int m0, int k0, int M, int tid)
{
    // A: 128 rows x 32 halves = 512 x 16B chunks; 2/thread
#pragma unroll
    for (int i = 0; i < 2; i++) {
        int f = i * 256 + tid;
        int row = f >> 2;
        int seg = (f & 3) * 8;
        int m = m0 + row;
        cp16(&as[row * AST2 + seg], g_hf + (size_t)m * HID + k0 + seg, m < M);
    }
    // B: 256 n-rows x 32 halves = 1024 chunks; 4/thread
#pragma unroll
    for (int i = 0; i < 4; i++) {
        int f = i * 256 + tid;
        int row = f >> 2;
        int seg = (f & 3) * 8;
        cp16(&bs[row * BST2 + seg], wt + (size_t)row * HID + k0 + seg, true);
    }
}

__global__ void __launch_bounds__(256, 1)
k_conv_f16(int layer, int M) {
    const __half* __restrict__ wt = g_wt + (size_t)layer * HID * HID;

    __shared__ __half As2[2][TBM * AST2];
    __shared__ __half Bs2[2][HID * BST2];

    const int tid  = threadIdx.x;
    const int lane = tid & 31;
    const int wid  = tid >> 5;
    const int wm0  = (wid & 1) * 64;
    const int wn0  = (wid >> 1) * 64;
    const int m0   = blockIdx.x * TBM;

    const int lq = lane >> 2;
    const int lr = lane & 3;

    float acc[4][8][4];
#pragma unroll
    for (int mt = 0; mt < 4; mt++)
#pragma unroll
        for (int nt = 0; nt < 8; nt++)
#pragma unroll
            for (int i = 0; i < 4; i++) acc[mt][nt][i] = 0.f;

    const int NIT = HID / TBK;   // 8

    conv_load_async(As2[0], Bs2[0], wt, m0, 0, M, tid);
    asm volatile("cp.async.commit_group;" ::: "memory");

    for (int it = 0; it < NIT; it++) {
        asm volatile("cp.async.wait_group 0;" ::: "memory");
        __syncthreads();
        if (it + 1 < NIT) {
            conv_load_async(As2[(it + 1) & 1], Bs2[(it + 1) & 1],
                            wt, m0, (it + 1) * TBK, M, tid);
            asm volatile("cp.async.commit_group;" ::: "memory");
        }
        const __half* __restrict__ as = As2[it & 1];
        const __half* __restrict__ bs = Bs2[it & 1];

#pragma unroll
        for (int ks = 0; ks < 2; ks++) {
            const int kc = ks * 16;
            uint32_t af[4][4];
#pragma unroll
            for (int mt = 0; mt < 4; mt++) {
                int r0 = wm0 + mt * 16 + lq;
                af[mt][0] = *(const uint32_t*)&as[(r0    ) * AST2 + kc + 2*lr    ];
                af[mt][1] = *(const uint32_t*)&as[(r0 + 8) * AST2 + kc + 2*lr    ];
                af[mt][2] = *(const uint32_t*)&as[(r0    ) * AST2 + kc + 2*lr + 8];
                af[mt][3] = *(const uint32_t*)&as[(r0 + 8) * AST2 + kc + 2*lr + 8];
            }
            uint32_t bf[8][2];
#pragma unroll
            for (int nt = 0; nt < 8; nt++) {
                int col = wn0 + nt * 8 + lq;
                bf[nt][0] = *(const uint32_t*)&bs[col * BST2 + kc + 2*lr    ];
                bf[nt][1] = *(const uint32_t*)&bs[col * BST2 + kc + 2*lr + 8];
            }
#pragma unroll
            for (int mt = 0; mt < 4; mt++)
#pragma unroll
                for (int nt = 0; nt < 8; nt++) {
                    float* c = acc[mt][nt];
                    asm volatile(
                        "mma.sync.aligned.m16n8k16.row.col.f32.f16.f16.f32 "
                        "{%0,%1,%2,%3}, {%4,%5,%6,%7}, {%8,%9}, {%0,%1,%2,%3};"
                        : "+f"(c[0]), "+f"(c[1]), "+f"(c[2]), "+f"(c[3])
                        : "r"(af[mt][0]), "r"(af[mt][1]),
                          "r"(af[mt][2]), "r"(af[mt][3]),
                          "r"(bf[nt][0]), "r"(bf[nt][1]));
                }
        }
        __syncthreads();
    }

    // Epilogue: *dis -> fp16 g_hw
#pragma unroll
    for (int mt = 0; mt < 4; mt++) {
        int r0 = m0 + wm0 + mt * 16 + lq;
        int r1 = r0 + 8;
        float d0 = (r0 < M) ? g_dis[r0] : 0.f;
        float d1 = (r1 < M) ? g_dis[r1] : 0.f;
#pragma unroll
        for (int nt = 0; nt < 8; nt++) {
            int col = wn0 + nt * 8 + 2 * lr;
            float* c = acc[mt][nt];
            if (r0 < M)
                *(__half2*)(g_hw + (size_t)r0 * HID + col) =
                    __floats2half2_rn(c[0] * d0, c[1] * d0);
            if (r1 < M)
                *(__half2*)(g_hw + (size_t)r1 * HID + col) =
                    __floats2half2_rn(c[2] * d1, c[3] * d1);
        }
    }
}

// ---------------------------------------------------------------------------
// Fused aggregate + finish: warp per node, fp16 gather / fp32 accumulate.
//   acc = hw[node] + sum_{r in CSR row} hw[r]
//   h = relu(LN(acc*dis + conv_b) * g + b) -> g_hf (fp16) or g_h (fp32, last)
// ---------------------------------------------------------------------------
__device__ __forceinline__ void acc_row(float* a, uint4 u) {
    const __half2* p = (const __half2*)&u;
#pragma unroll
    for (int i = 0; i < 4; i++) {
        float2 f = __half22float2(p[i]);
        a[2 * i]     += f.x;
        a[2 * i + 1] += f.y;
    }
}

__global__ void __launch_bounds__(256)
k_agg_finish(const float* __restrict__ cb, const float* __restrict__ lg,
             const float* __restrict__ lb, int n, int store32) {
    int node = (blockIdx.x * blockDim.x + threadIdx.x) >> 5;
    if (node >= n) return;
    int lane = threadIdx.x & 31;
    size_t base = (size_t)node * HID;

    float a[8];
#pragma unroll
    for (int i = 0; i < 8; i++) a[i] = 0.f;

    acc_row(a, __ldg((const uint4*)(g_hw + base) + lane));   // self-loop

    int e   = g_rowptr[node];
    int end = g_rowptr[node + 1];

    for (; e + 3 < end; e += 4) {
        int r0 = __ldg(&g_csr[e]);
        int r1 = __ldg(&g_csr[e + 1]);
        int r2 = __ldg(&g_csr[e + 2]);
        int r3 = __ldg(&g_csr[e + 3]);
        uint4 u0 = __ldg((const uint4*)(g_hw + (size_t)r0 * HID) + lane);
        uint4 u1 = __ldg((const uint4*)(g_hw + (size_t)r1 * HID) + lane);
        uint4 u2 = __ldg((const uint4*)(g_hw + (size_t)r2 * HID) + lane);
        uint4 u3 = __ldg((const uint4*)(g_hw + (size_t)r3 * HID) + lane);
        acc_row(a, u0); acc_row(a, u1); acc_row(a, u2); acc_row(a, u3);
    }
    for (; e < end; e++) {
        int r0 = __ldg(&g_csr[e]);
        acc_row(a, __ldg((const uint4*)(g_hw + (size_t)r0 * HID) + lane));
    }

    float d = g_dis[node];
    float4 c0 = ((const float4*)cb)[lane * 2];
    float4 c1 = ((const float4*)cb)[lane * 2 + 1];

    float v[8];
    v[0] = a[0] * d + c0.x; v[1] = a[1] * d + c0.y;
    v[2] = a[2] * d + c0.z; v[3] = a[3] * d + c0.w;
    v[4] = a[4] * d + c1.x; v[5] = a[5] * d + c1.y;
    v[6] = a[6] * d + c1.z; v[7] = a[7] * d + c1.w;

    float s = 0.f, sq = 0.f;
#pragma unroll
    for (int i = 0; i < 8; i++) { s += v[i]; sq += v[i] * v[i]; }
#pragma unroll
    for (int o = 16; o > 0; o >>= 1) {
        s  += __shfl_xor_sync(0xffffffffu, s, o);
        sq += __shfl_xor_sync(0xffffffffu, sq, o);
    }
    float mu = s * (1.f / HID);
    float var = sq * (1.f / HID) - mu * mu;
    float rs = rsqrtf(var + LN_EPS);

    float4 g0 = ((const float4*)lg)[lane * 2];
    float4 g1 = ((const float4*)lg)[lane * 2 + 1];
    float4 b0 = ((const float4*)lb)[lane * 2];
    float4 b1 = ((const float4*)lb)[lane * 2 + 1];

    float o0[4], o1[4];
    o0[0] = fmaxf((v[0] - mu) * rs * g0.x + b0.x, 0.f);
    o0[1] = fmaxf((v[1] - mu) * rs * g0.y + b0.y, 0.f);
    o0[2] = fmaxf((v[2] - mu) * rs * g0.z + b0.z, 0.f);
    o0[3] = fmaxf((v[3] - mu) * rs * g0.w + b0.w, 0.f);
    o1[0] = fmaxf((v[4] - mu) * rs * g1.x + b1.x, 0.f);
    o1[1] = fmaxf((v[5] - mu) * rs * g1.y + b1.y, 0.f);
    o1[2] = fmaxf((v[6] - mu) * rs * g1.z + b1.z, 0.f);
    o1[3] = fmaxf((v[7] - mu) * rs * g1.w + b1.w, 0.f);

    if (store32) {  // last layer: fp32 for split-precision lin1
        *(float4*)(g_h + base + lane * 8)     = *(float4*)o0;
        *(float4*)(g_h + base + lane * 8 + 4) = *(float4*)o1;
    } else {        // fp16 for next conv layer
        __half2 p[4];
        p[0] = __floats2half2_rn(o0[0], o0[1]);
        p[1] = __floats2half2_rn(o0[2], o0[3]);
        p[2] = __floats2half2_rn(o1[0], o1[1]);
        p[3] = __floats2half2_rn(o1[2], o1[3]);
        *(uint4*)(g_hf + base + lane * 8) = *(uint4*)p;
    }
}

// ---------------------------------------------------------------------------
// lin2: out[n] = h1[n,:] . w + b, warp per node (128-dot)
// ---------------------------------------------------------------------------
__global__ void __launch_bounds__(256)
k_lin2(const float* __restrict__ w, const float* __restrict__ b,
       float* __restrict__ out, int n) {
    int node = (blockIdx.x * blockDim.x + threadIdx.x) >> 5;
    if (node >= n) return;
    int lane = threadIdx.x & 31;

    float4 h = *(const float4*)(g_h1 + (size_t)node * (HID / 2) + lane * 4);
    float4 wv = ((const float4*)w)[lane];
    float s = h.x * wv.x + h.y * wv.y + h.z * wv.z + h.w * wv.w;
#pragma unroll
    for (int o = 16; o > 0; o >>= 1)
        s += __shfl_xor_sync(0xffffffffu, s, o);
    if (lane == 0) out[node] = s + b[0];
}

// ---------------------------------------------------------------------------
// Launch
// ---------------------------------------------------------------------------
extern "C" void kernel_launch(void* const* d_in, const int* in_sizes, int n_in,
                              void* d_out, int out_size) {
    const float* x      = (const float*)d_in[0];
    const void*  ei     = d_in[1];                 // int32 or int64 — probed
    const float* enc_w  = (const float*)d_in[2];
    const float* enc_b  = (const float*)d_in[3];
    const float* conv_w = (const float*)d_in[4];
    const float* conv_b = (const float*)d_in[5];
    const float* ln_g   = (const float*)d_in[6];
    const float* ln_b   = (const float*)d_in[7];
    const float* lin1_w = (const float*)d_in[8];
    const float* lin1_b = (const float*)d_in[9];
    const float* lin2_w = (const float*)d_in[10];
    const float* lin2_b = (const float*)d_in[11];
    float* out = (float*)d_out;

    const int N = in_sizes[0] / IN_C;    // 100000
    const int E = in_sizes[1] / 2;       // 1600000

    int nsamp = (E >= 1024) ? 1024 : (E > 0 ? E : 1);
    k_detect<<<1, 256>>>((const long long*)ei, nsamp, N);

    // Degree + normalization + CSR (recomputed every call: deterministic)
    const int nblk = (N + 255) / 256;
    k_deg_init<<<nblk, 256>>>(N);
    k_deg_count<<<(E + 255) / 256, 256>>>(ei, E, N);
    k_dis<<<nblk, 256>>>(N);
    k_scan1<<<nblk, 256>>>(N);
    k_scan2<<<1, 1024>>>(nblk, N);
    k_scan3<<<nblk, 256>>>(N);
    k_fill<<<(E + 255) / 256, 256>>>(ei, E, N);

    // Conv weights -> transposed fp16
    k_wt_convert<<<(NLAYERS * HID * HID) / 256, 256>>>(conv_w);

    const int tf32_blocks = (N + TBM - 1) / TBM;

    // Encoder: g_hf = half(x @ enc_w + enc_b)   (tf32, K=128)
    k_gemm_tf32<256, false><<<tf32_blocks, 256>>>(x, enc_w, enc_b, N, IN_C, 0);

    const int node_warp_blocks = (N * 32 + 255) / 256;

    for (int i = 0; i < NLAYERS; i++) {
        // hw = half((g_hf @ W_i) * dis)   (fp16 mma, K=256; layer idx passed,
        // weight pointer formed in device code)
        k_conv_f16<<<tf32_blocks, 256>>>(i, N);
        // h = relu(LN((hw[node] + sum_neighbors hw)*dis + b))
        k_agg_finish<<<node_warp_blocks, 256>>>(conv_b + (size_t)i * HID,
                                                ln_g + (size_t)i * HID,
                                                ln_b + (size_t)i * HID, N,
                                                i == NLAYERS - 1 ? 1 : 0);
    }

    // lin1 (+relu) 3xTF32 split-precision (TBN=128), then lin2
    k_gemm_tf32<128, true><<<tf32_blocks, 256>>>(nullptr, lin1_w, lin1_b,
                                                 N, HID, 2);
    k_lin2<<<node_warp_blocks, 256>>>(lin2_w, lin2_b, out, N);
}

// round 17
// speedup vs baseline: 4.5269x; 1.0316x over previous
#include <cuda_runtime.h>
#include <cuda_fp16.h>
#include <cstdint>

// ---------------------------------------------------------------------------
// StressGCN: 4-layer GCN, N=100000 nodes, E=1.6M edges, IN_C=128, HID=256.
// h = relu(LN(agg(h@W)*dis + b)) x4, bracketed by encoder / lin1+relu / lin2.
// CSR gather aggregation (dis applied per-row at gather time). Encoder: tf32
// mma. Conv: fp16 mma m16n8k16 (fp32 accum). lin1: 3xTF32 split precision.
// CSR build overlapped with encoder/conv0 via a fork/join side stream.
// NOTE: device globals (g_*) referenced ONLY from device code (R15 bug: host
// address of __device__ symbol silently reads zero host memory via ATS).
// ---------------------------------------------------------------------------

#define NNODES   100000
#define EMAX     1700000
#define IN_C     128
#define HID      256
#define NLAYERS  4
#define LN_EPS   1e-5f

// Scratch (device globals: allocation is forbidden)
__device__ float  g_h  [(size_t)NNODES * HID];      // fp32 h (last layer only)
__device__ __half g_hf [(size_t)NNODES * HID];      // fp16 h (conv A operand)
__device__ __half g_hw [(size_t)NNODES * HID];      // h@W, fp16 (gather src)
__device__ float  g_h1 [(size_t)NNODES * (HID/2)];  // lin1 output
__device__ __half g_wt [(size_t)NLAYERS * HID * HID]; // conv_w transposed fp16
__device__ float  g_dis[NNODES];
__device__ int    g_deg[NNODES];                    // 1 + in-degree
__device__ int    g_rowptr[NNODES + 1];
__device__ int    g_cursor[NNODES];
__device__ int    g_blocksum[1024];
__device__ int    g_csr[EMAX];                      // source node per edge slot
__device__ int    g_is32;                           // 1 if edge_index is int32

// ---------------------------------------------------------------------------
// Probe + degree init fused: all blocks init deg=1; block 0 probes dtype.
// ---------------------------------------------------------------------------
__global__ void k_detect_init(const long long* __restrict__ ei, int nsamp,
                              int n, int N) {
    int i = blockIdx.x * blockDim.x + threadIdx.x;
    if (i < n) g_deg[i] = 1;   // self loop
    if (blockIdx.x == 0) {
        __shared__ int bad;
        if (threadIdx.x == 0) bad = 0;
        __syncthreads();
        for (int j = threadIdx.x; j < nsamp; j += blockDim.x) {
            long long v = ei[j];
            if (v < 0 || v >= (long long)N) bad = 1;
        }
        __syncthreads();
        if (threadIdx.x == 0) g_is32 = bad;
    }
}

__device__ __forceinline__ int edge_at(const void* ei, size_t pos, int is32) {
    return is32 ? ((const int*)ei)[pos]
                : (int)(((const long long*)ei)[pos]);
}

__global__ void k_deg_count(const void* __restrict__ ei, int E, int N) {
    int e = blockIdx.x * blockDim.x + threadIdx.x;
    if (e >= E) return;
    int c = edge_at(ei, (size_t)E + e, g_is32);   // target
    if ((unsigned)c < (unsigned)N)
        atomicAdd(&g_deg[c], 1);
}

// Exclusive scan of (deg-1) [edge-only degree] + fused dis = rsqrt(deg).
__global__ void k_scan1(int n) {
    __shared__ int s[256];
    int idx = blockIdx.x * 256 + threadIdx.x;
    int deg = (idx < n) ? g_deg[idx] : 1;
    int v = deg - 1;
    s[threadIdx.x] = v;
    __syncthreads();
#pragma unroll
    for (int off = 1; off < 256; off <<= 1) {
        int t = (threadIdx.x >= off) ? s[threadIdx.x - off] : 0;
        __syncthreads();
        s[threadIdx.x] += t;
        __syncthreads();
    }
    if (idx < n) {
        g_rowptr[idx] = s[threadIdx.x] - v;   // exclusive
        g_dis[idx] = rsqrtf((float)deg);
    }
    if (threadIdx.x == 255) g_blocksum[blockIdx.x] = s[255];
}

__global__ void k_scan2(int nb, int N) {
    __shared__ int s[1024];
    int tid = threadIdx.x;
    int v = (tid < nb) ? g_blocksum[tid] : 0;
    s[tid] = v;
    __syncthreads();
#pragma unroll
    for (int off = 1; off < 1024; off <<= 1) {
        int t = (tid >= off) ? s[tid - off] : 0;
        __syncthreads();
        s[tid] += t;
        __syncthreads();
    }
    if (tid < nb) g_blocksum[tid] = s[tid] - v;        // exclusive
    if (tid == nb - 1) g_rowptr[N] = s[tid];           // total edge count
}

__global__ void k_scan3(int n) {
    int idx = blockIdx.x * blockDim.x + threadIdx.x;
    if (idx < n) {
        int r = g_rowptr[idx] + g_blocksum[blockIdx.x];
        g_rowptr[idx] = r;
        g_cursor[idx] = r;
    }
}

__global__ void k_fill(const void* __restrict__ ei, int E, int N) {
    int e = blockIdx.x * blockDim.x + threadIdx.x;
    if (e >= E) return;
    int is32 = g_is32;
    int r = edge_at(ei, e, is32);
    int c = edge_at(ei, (size_t)E + e, is32);
    if ((unsigned)r >= (unsigned)N || (unsigned)c >= (unsigned)N) return;
    int pos = atomicAdd(&g_cursor[c], 1);
    if (pos < EMAX) g_csr[pos] = r;
}

// Transpose + fp16-convert conv weights: g_wt[l][n][k] = conv_w[l][k][n]
__global__ void k_wt_convert(const float* __restrict__ w) {
    int idx = blockIdx.x * blockDim.x + threadIdx.x;  // L*HID*HID threads
    int l = idx >> 16;
    int k = (idx >> 8) & 255;
    int n = idx & 255;
    g_wt[((size_t)l * HID + n) * HID + k] = __float2half(w[idx]);
}

// ---------------------------------------------------------------------------
// cp.async helper (16B, zero-fill when !pred)
// ---------------------------------------------------------------------------
__device__ __forceinline__ void cp16(void* smem, const void* g, bool pred) {
    uint32_t s = (uint32_t)__cvta_generic_to_shared(smem);
    int sz = pred ? 16 : 0;
    asm volatile("cp.async.cg.shared.global [%0], [%1], 16, %2;"
                 :: "r"(s), "l"(g), "r"(sz));
}

// ---------------------------------------------------------------------------
// TF32 tensor-core GEMM, cp.async double-buffered.
// mode 0: g_hf = half(C + bias)   (encoder, TBN_=256, A=x fp32)
// mode 2: g_h1 = relu(C + bias)   (lin1, TBN_=128, A=g_h fp32, SPLIT=3xTF32)
// ---------------------------------------------------------------------------
#define TBM 128
#define TBK 32
#define ASTRIDE 36   // fragment LDS conflict-free, float4-aligned

template <int TBN_>
__device__ __forceinline__ void load_tiles_async(
    float* __restrict__ as, float* __restrict__ bs,
    const float* __restrict__ A, const float* __restrict__ B,
    int m0, int k0, int M, int K, int tid)
{
    constexpr int BSTRIDE_ = TBN_ + 8;
#pragma unroll
    for (int i = 0; i < 4; i++) {
        int f = i * 256 + tid;
        int row = f >> 3;
        int c4 = (f & 7) * 4;
        int m = m0 + row;
        cp16(&as[row * ASTRIDE + c4], A + (size_t)m * K + k0 + c4, m < M);
    }
#pragma unroll
    for (int i = 0; i < TBN_ / 32; i++) {
        int f = i * 256 + tid;
        int row = f / (TBN_ / 4);
        int c4 = (f % (TBN_ / 4)) * 4;
        cp16(&bs[row * BSTRIDE_ + c4], B + (size_t)(k0 + row) * TBN_ + c4, true);
    }
}

__device__ __forceinline__ void mma_tf32(float* c, const uint32_t* a,
                                         const uint32_t* b) {
    asm volatile(
        "mma.sync.aligned.m16n8k8.row.col.f32.tf32.tf32.f32 "
        "{%0,%1,%2,%3}, {%4,%5,%6,%7}, {%8,%9}, {%0,%1,%2,%3};"
        : "+f"(c[0]), "+f"(c[1]), "+f"(c[2]), "+f"(c[3])
        : "r"(a[0]), "r"(a[1]), "r"(a[2]), "r"(a[3]), "r"(b[0]), "r"(b[1]));
}

template <int TBN_, bool SPLIT>
__global__ void __launch_bounds__(256, 1)
k_gemm_tf32(const float* __restrict__ Aext, const float* __restrict__ B,
            const float* __restrict__ bias, int M, int K, int mode) {
    constexpr int BSTRIDE_ = TBN_ + 8;
    constexpr int NT = TBN_ / 32;
    const float* __restrict__ A = Aext ? Aext : g_h;

    __shared__ float As[2][TBM * ASTRIDE];
    __shared__ float Bs[2][TBK * BSTRIDE_];

    const int tid  = threadIdx.x;
    const int lane = tid & 31;
    const int wid  = tid >> 5;
    const int wm0  = (wid & 1) * 64;
    const int wn0  = (wid >> 1) * (TBN_ / 4);
    const int m0   = blockIdx.x * TBM;

    const int lq = lane >> 2;
    const int lr = lane & 3;

    float acc[4][NT][4];
#pragma unroll
    for (int mt = 0; mt < 4; mt++)
#pragma unroll
        for (int nt = 0; nt < NT; nt++)
#pragma unroll
            for (int i = 0; i < 4; i++) acc[mt][nt][i] = 0.f;

    const int NIT = K / TBK;

    load_tiles_async<TBN_>(As[0], Bs[0], A, B, m0, 0, M, K, tid);
    asm volatile("cp.async.commit_group;" ::: "memory");

    for (int it = 0; it < NIT; it++) {
        asm volatile("cp.async.wait_group 0;" ::: "memory");
        __syncthreads();
        if (it + 1 < NIT) {
            load_tiles_async<TBN_>(As[(it + 1) & 1], Bs[(it + 1) & 1],
                                   A, B, m0, (it + 1) * TBK, M, K, tid);
            asm volatile("cp.async.commit_group;" ::: "memory");
        }
        const float* __restrict__ as = As[it & 1];
        const float* __restrict__ bs = Bs[it & 1];

#pragma unroll
        for (int ks = 0; ks < 4; ks++) {
            const int kc = ks * 8;
            uint32_t af[4][4];
#pragma unroll
            for (int mt = 0; mt < 4; mt++) {
                int r0 = wm0 + mt * 16 + lq;
                af[mt][0] = __float_as_uint(as[(r0    ) * ASTRIDE + kc + lr    ]);
                af[mt][1] = __float_as_uint(as[(r0 + 8) * ASTRIDE + kc + lr    ]);
                af[mt][2] = __float_as_uint(as[(r0    ) * ASTRIDE + kc + lr + 4]);
                af[mt][3] = __float_as_uint(as[(r0 + 8) * ASTRIDE + kc + lr + 4]);
            }
            uint32_t bf[NT][2];
#pragma unroll
            for (int nt = 0; nt < NT; nt++) {
                int col = wn0 + nt * 8 + lq;
                bf[nt][0] = __float_as_uint(bs[(kc + lr    ) * BSTRIDE_ + col]);
                bf[nt][1] = __float_as_uint(bs[(kc + lr + 4) * BSTRIDE_ + col]);
            }
            if (!SPLIT) {
#pragma unroll
                for (int mt = 0; mt < 4; mt++)
#pragma unroll
                    for (int nt = 0; nt < NT; nt++)
                        mma_tf32(acc[mt][nt], af[mt], bf[nt]);
            } else {
                uint32_t ah[4][4], al[4][4], bh[NT][2], bl[NT][2];
#pragma unroll
                for (int mt = 0; mt < 4; mt++)
#pragma unroll
                    for (int i = 0; i < 4; i++) {
                        uint32_t h = af[mt][i] & 0xffffe000u;
                        ah[mt][i] = h;
                        al[mt][i] = __float_as_uint(
                            __uint_as_float(af[mt][i]) - __uint_as_float(h));
                    }
#pragma unroll
                for (int nt = 0; nt < NT; nt++)
#pragma unroll
                    for (int i = 0; i < 2; i++) {
                        uint32_t h = bf[nt][i] & 0xffffe000u;
                        bh[nt][i] = h;
                        bl[nt][i] = __float_as_uint(
                            __uint_as_float(bf[nt][i]) - __uint_as_float(h));
                    }
#pragma unroll
                for (int mt = 0; mt < 4; mt++)
#pragma unroll
                    for (int nt = 0; nt < NT; nt++) {
                        mma_tf32(acc[mt][nt], al[mt], bh[nt]);
                        mma_tf32(acc[mt][nt], ah[mt], bl[nt]);
                        mma_tf32(acc[mt][nt], ah[mt], bh[nt]);
                    }
            }
        }
        __syncthreads();
    }

#pragma unroll
    for (int mt = 0; mt < 4; mt++) {
        int r0 = m0 + wm0 + mt * 16 + lq;
        int r1 = r0 + 8;
#pragma unroll
        for (int nt = 0; nt < NT; nt++) {
            int col = wn0 + nt * 8 + 2 * lr;
            float2 bv = *(const float2*)(bias + col);
            float* c = acc[mt][nt];
            if (mode == 0) {          // encoder -> fp16 g_hf
                if (r0 < M)
                    *(__half2*)(g_hf + (size_t)r0 * TBN_ + col) =
                        __floats2half2_rn(c[0] + bv.x, c[1] + bv.y);
                if (r1 < M)
                    *(__half2*)(g_hf + (size_t)r1 * TBN_ + col) =
                        __floats2half2_rn(c[2] + bv.x, c[3] + bv.y);
            } else {                  // lin1 -> relu fp32 g_h1
                if (r0 < M) {
                    float2 v = make_float2(fmaxf(c[0] + bv.x, 0.f),
                                           fmaxf(c[1] + bv.y, 0.f));
                    *(float2*)(g_h1 + (size_t)r0 * TBN_ + col) = v;
                }
                if (r1 < M) {
                    float2 v = make_float2(fmaxf(c[2] + bv.x, 0.f),
                                           fmaxf(c[3] + bv.y, 0.f));
                    *(float2*)(g_h1 + (size_t)r1 * TBN_ + col) = v;
                }
            }
        }
    }
}

// ---------------------------------------------------------------------------
// FP16 conv GEMM: g_hw = half(g_hf @ Wt^T) — NO dis here (applied at gather,
// removing the CSR/dis dependency so conv0 overlaps the CSR build).
// Block tile 128x256x64(half), double-buffered; mma.m16n8k16 fp32-accum.
// ---------------------------------------------------------------------------
#define CTBK 64
#define AST2 72   // 64 + 8 halves: fragment uint32 LDS conflict-free, 16B rows

__device__ __forceinline__ void conv_load_async(
    __half* __restrict__ as, __half* __restrict__ bs,
    const __half* __restrict__ wt, int m0, int k0, int M, int tid)
{
    // A: 128 rows x 64 halves = 1024 x 16B chunks; 4/thread
#pragma unroll
    for (int i = 0; i < 4; i++) {
        int f = i * 256 + tid;
        int row = f >> 3;
        int seg = (f & 7) * 8;
        int m = m0 + row;
        cp16(&as[row * AST2 + seg], g_hf + (size_t)m * HID + k0 + seg, m < M);
    }
    // B: 256 n-rows x 64 halves = 2048 chunks; 8/thread
#pragma unroll
    for (int i = 0; i < 8; i++) {
        int f = i * 256 + tid;
        int row = f >> 3;
        int seg = (f & 7) * 8;
        cp16(&bs[row * AST2 + seg], wt + (size_t)row * HID + k0 + seg, true);
    }
}

__global__ void __launch_bounds__(256, 1)
k_conv_f16(int layer, int M) {
    const __half* __restrict__ wt = g_wt + (size_t)layer * HID * HID;

    __shared__ __half As2[2][TBM * AST2];
    __shared__ __half Bs2[2][HID * AST2];

    const int tid  = threadIdx.x;
    const int lane = tid & 31;
    const int wid  = tid >> 5;
    const int wm0  = (wid & 1) * 64;
    const int wn0  = (wid >> 1) * 64;
    const int m0   = blockIdx.x * TBM;

    const int lq = lane >> 2;
    const int lr = lane & 3;

    float acc[4][8][4];
#pragma unroll
    for (int mt = 0; mt < 4; mt++)
#pragma unroll
        for (int nt = 0; nt < 8; nt++)
#pragma unroll
            for (int i = 0; i < 4; i++) acc[mt][nt][i] = 0.f;

    const int NIT = HID / CTBK;   // 4

    conv_load_async(As2[0], Bs2[0], wt, m0, 0, M, tid);
    asm volatile("cp.async.commit_group;" ::: "memory");

    for (int it = 0; it < NIT; it++) {
        asm volatile("cp.async.wait_group 0;" ::: "memory");
        __syncthreads();
        if (it + 1 < NIT) {
            conv_load_async(As2[(it + 1) & 1], Bs2[(it + 1) & 1],
                            wt, m0, (it + 1) * CTBK, M, tid);
            asm volatile("cp.async.commit_group;" ::: "memory");
        }
        const __half* __restrict__ as = As2[it & 1];
        const __half* __restrict__ bs = Bs2[it & 1];

#pragma unroll
        for (int ks = 0; ks < 4; ks++) {
            const int kc = ks * 16;
            uint32_t af[4][4];
#pragma unroll
            for (int mt = 0; mt < 4; mt++) {
                int r0 = wm0 + mt * 16 + lq;
                af[mt][0] = *(const uint32_t*)&as[(r0    ) * AST2 + kc + 2*lr    ];
                af[mt][1] = *(const uint32_t*)&as[(r0 + 8) * AST2 + kc + 2*lr    ];
                af[mt][2] = *(const uint32_t*)&as[(r0    ) * AST2 + kc + 2*lr + 8];
                af[mt][3] = *(const uint32_t*)&as[(r0 + 8) * AST2 + kc + 2*lr + 8];
            }
            uint32_t bf[8][2];
#pragma unroll
            for (int nt = 0; nt < 8; nt++) {
                int col = wn0 + nt * 8 + lq;
                bf[nt][0] = *(const uint32_t*)&bs[col * AST2 + kc + 2*lr    ];
                bf[nt][1] = *(const uint32_t*)&bs[col * AST2 + kc + 2*lr + 8];
            }
#pragma unroll
            for (int mt = 0; mt < 4; mt++)
#pragma unroll
                for (int nt = 0; nt < 8; nt++) {
                    float* c = acc[mt][nt];
                    asm volatile(
                        "mma.sync.aligned.m16n8k16.row.col.f32.f16.f16.f32 "
                        "{%0,%1,%2,%3}, {%4,%5,%6,%7}, {%8,%9}, {%0,%1,%2,%3};"
                        : "+f"(c[0]), "+f"(c[1]), "+f"(c[2]), "+f"(c[3])
                        : "r"(af[mt][0]), "r"(af[mt][1]),
                          "r"(af[mt][2]), "r"(af[mt][3]),
                          "r"(bf[nt][0]), "r"(bf[nt][1]));
                }
        }
        __syncthreads();
    }

    // Epilogue: raw product -> fp16 g_hw (no dis)
#pragma unroll
    for (int mt = 0; mt < 4; mt++) {
        int r0 = m0 + wm0 + mt * 16 + lq;
        int r1 = r0 + 8;
#pragma unroll
        for (int nt = 0; nt < 8; nt++) {
            int col = wn0 + nt * 8 + 2 * lr;
            float* c = acc[mt][nt];
            if (r0 < M)
                *(__half2*)(g_hw + (size_t)r0 * HID + col) =
                    __floats2half2_rn(c[0], c[1]);
            if (r1 < M)
                *(__half2*)(g_hw + (size_t)r1 * HID + col) =
                    __floats2half2_rn(c[2], c[3]);
        }
    }
}

// ---------------------------------------------------------------------------
// Fused aggregate + finish: warp per node, fp16 gather / fp32 accumulate,
// per-row dis scaling at gather:  a = dis[node]*hw[node] + Σ dis[r]*hw[r]
//   h = relu(LN(a*dis[node] + conv_b) * g + b) -> g_hf (fp16) / g_h (last)
// ---------------------------------------------------------------------------
__device__ __forceinline__ void acc_row(float* a, uint4 u, float s) {
    const __half2* p = (const __half2*)&u;
#pragma unroll
    for (int i = 0; i < 4; i++) {
        float2 f = __half22float2(p[i]);
        a[2 * i]     += s * f.x;
        a[2 * i + 1] += s * f.y;
    }
}

__global__ void __launch_bounds__(256)
k_agg_finish(const float* __restrict__ cb, const float* __restrict__ lg,
             const float* __restrict__ lb, int n, int store32) {
    int node = (blockIdx.x * blockDim.x + threadIdx.x) >> 5;
    if (node >= n) return;
    int lane = threadIdx.x & 31;
    size_t base = (size_t)node * HID;

    float a[8];
#pragma unroll
    for (int i = 0; i < 8; i++) a[i] = 0.f;

    float d = g_dis[node];
    acc_row(a, __ldg((const uint4*)(g_hw + base) + lane), d);  // self-loop

    int e   = g_rowptr[node];
    int end = g_rowptr[node + 1];

    for (; e + 3 < end; e += 4) {
        int r0 = __ldg(&g_csr[e]);
        int r1 = __ldg(&g_csr[e + 1]);
        int r2 = __ldg(&g_csr[e + 2]);
        int r3 = __ldg(&g_csr[e + 3]);
        float d0 = __ldg(&g_dis[r0]);
        float d1 = __ldg(&g_dis[r1]);
        float d2 = __ldg(&g_dis[r2]);
        float d3 = __ldg(&g_dis[r3]);
        uint4 u0 = __ldg((const uint4*)(g_hw + (size_t)r0 * HID) + lane);
        uint4 u1 = __ldg((const uint4*)(g_hw + (size_t)r1 * HID) + lane);
        uint4 u2 = __ldg((const uint4*)(g_hw + (size_t)r2 * HID) + lane);
        uint4 u3 = __ldg((const uint4*)(g_hw + (size_t)r3 * HID) + lane);
        acc_row(a, u0, d0); acc_row(a, u1, d1);
        acc_row(a, u2, d2); acc_row(a, u3, d3);
    }
    for (; e < end; e++) {
        int r0 = __ldg(&g_csr[e]);
        float d0 = __ldg(&g_dis[r0]);
        acc_row(a, __ldg((const uint4*)(g_hw + (size_t)r0 * HID) + lane), d0);
    }

    float4 c0 = ((const float4*)cb)[lane * 2];
    float4 c1 = ((const float4*)cb)[lane * 2 + 1];

    float v[8];
    v[0] = a[0] * d + c0.x; v[1] = a[1] * d + c0.y;
    v[2] = a[2] * d + c0.z; v[3] = a[3] * d + c0.w;
    v[4] = a[4] * d + c1.x; v[5] = a[5] * d + c1.y;
    v[6] = a[6] * d + c1.z; v[7] = a[7] * d + c1.w;

    float s = 0.f, sq = 0.f;
#pragma unroll
    for (int i = 0; i < 8; i++) { s += v[i]; sq += v[i] * v[i]; }
#pragma unroll
    for (int o = 16; o > 0; o >>= 1) {
        s  += __shfl_xor_sync(0xffffffffu, s, o);
        sq += __shfl_xor_sync(0xffffffffu, sq, o);
    }
    float mu = s * (1.f / HID);
    float var = sq * (1.f / HID) - mu * mu;
    float rs = rsqrtf(var + LN_EPS);

    float4 g0 = ((const float4*)lg)[lane * 2];
    float4 g1 = ((const float4*)lg)[lane * 2 + 1];
    float4 b0 = ((const float4*)lb)[lane * 2];
    float4 b1 = ((const float4*)lb)[lane * 2 + 1];

    float o0[4], o1[4];
    o0[0] = fmaxf((v[0] - mu) * rs * g0.x + b0.x, 0.f);
    o0[1] = fmaxf((v[1] - mu) * rs * g0.y + b0.y, 0.f);
    o0[2] = fmaxf((v[2] - mu) * rs * g0.z + b0.z, 0.f);
    o0[3] = fmaxf((v[3] - mu) * rs * g0.w + b0.w, 0.f);
    o1[0] = fmaxf((v[4] - mu) * rs * g1.x + b1.x, 0.f);
    o1[1] = fmaxf((v[5] - mu) * rs * g1.y + b1.y, 0.f);
    o1[2] = fmaxf((v[6] - mu) * rs * g1.z + b1.z, 0.f);
    o1[3] = fmaxf((v[7] - mu) * rs * g1.w + b1.w, 0.f);

    if (store32) {  // last layer: fp32 for split-precision lin1
        *(float4*)(g_h + base + lane * 8)     = *(float4*)o0;
        *(float4*)(g_h + base + lane * 8 + 4) = *(float4*)o1;
    } else {        // fp16 for next conv layer
        __half2 p[4];
        p[0] = __floats2half2_rn(o0[0], o0[1]);
        p[1] = __floats2half2_rn(o0[2], o0[3]);
        p[2] = __floats2half2_rn(o1[0], o1[1]);
        p[3] = __floats2half2_rn(o1[2], o1[3]);
        *(uint4*)(g_hf + base + lane * 8) = *(uint4*)p;
    }
}

// ---------------------------------------------------------------------------
// lin2: out[n] = h1[n,:] . w + b, warp per node (128-dot)
// ---------------------------------------------------------------------------
__global__ void __launch_bounds__(256)
k_lin2(const float* __restrict__ w, const float* __restrict__ b,
       float* __restrict__ out, int n) {
    int node = (blockIdx.x * blockDim.x + threadIdx.x) >> 5;
    if (node >= n) return;
    int lane = threadIdx.x & 31;

    float4 h = *(const float4*)(g_h1 + (size_t)node * (HID / 2) + lane * 4);
    float4 wv = ((const float4*)w)[lane];
    float s = h.x * wv.x + h.y * wv.y + h.z * wv.z + h.w * wv.w;
#pragma unroll
    for (int o = 16; o > 0; o >>= 1)
        s += __shfl_xor_sync(0xffffffffu, s, o);
    if (lane == 0) out[node] = s + b[0];
}

// ---------------------------------------------------------------------------
// Launch: CSR build forked to a side stream, joined before first aggregate.
// ---------------------------------------------------------------------------
extern "C" void kernel_launch(void* const* d_in, const int* in_sizes, int n_in,
                              void* d_out, int out_size) {
    const float* x      = (const float*)d_in[0];
    const void*  ei     = d_in[1];                 // int32 or int64 — probed
    const float* enc_w  = (const float*)d_in[2];
    const float* enc_b  = (const float*)d_in[3];
    const float* conv_w = (const float*)d_in[4];
    const float* conv_b = (const float*)d_in[5];
    const float* ln_g   = (const float*)d_in[6];
    const float* ln_b   = (const float*)d_in[7];
    const float* lin1_w = (const float*)d_in[8];
    const float* lin1_b = (const float*)d_in[9];
    const float* lin2_w = (const float*)d_in[10];
    const float* lin2_b = (const float*)d_in[11];
    float* out = (float*)d_out;

    const int N = in_sizes[0] / IN_C;    // 100000
    const int E = in_sizes[1] / 2;       // 1600000

    // Side stream + fork/join events (created once, on the uncaptured
    // correctness call; identical GPU work every call).
    static cudaStream_t sA = nullptr;
    static cudaEvent_t evFork = nullptr, evJoin = nullptr;
    if (sA == nullptr) {
        cudaStreamCreateWithFlags(&sA, cudaStreamNonBlocking);
        cudaEventCreateWithFlags(&evFork, cudaEventDisableTiming);
        cudaEventCreateWithFlags(&evJoin, cudaEventDisableTiming);
    }

    const int nblk = (N + 255) / 256;
    const int eblk = (E + 255) / 256;
    int nsamp = (E >= 1024) ? 1024 : (E > 0 ? E : 1);

    // ---- fork: CSR build on side stream -----------------------------------
    cudaEventRecord(evFork, 0);
    cudaStreamWaitEvent(sA, evFork, 0);
    k_detect_init<<<nblk, 256, 0, sA>>>((const long long*)ei, nsamp, N, N);
    k_deg_count<<<eblk, 256, 0, sA>>>(ei, E, N);
    k_scan1<<<nblk, 256, 0, sA>>>(N);
    k_scan2<<<1, 1024, 0, sA>>>(nblk, N);
    k_scan3<<<nblk, 256, 0, sA>>>(N);
    k_fill<<<eblk, 256, 0, sA>>>(ei, E, N);
    cudaEventRecord(evJoin, sA);

    // ---- main stream: weights + encoder + conv0 (no CSR/dis dependency) ---
    const int tf32_blocks = (N + TBM - 1) / TBM;
    k_wt_convert<<<(NLAYERS * HID * HID) / 256, 256>>>(conv_w);
    k_gemm_tf32<256, false><<<tf32_blocks, 256>>>(x, enc_w, enc_b, N, IN_C, 0);
    k_conv_f16<<<tf32_blocks, 256>>>(0, N);

    // ---- join: aggregation needs CSR + dis --------------------------------
    cudaStreamWaitEvent(0, evJoin, 0);

    const int node_warp_blocks = (N * 32 + 255) / 256;
    for (int i = 0; i < NLAYERS; i++) {
        if (i > 0) k_conv_f16<<<tf32_blocks, 256>>>(i, N);
        k_agg_finish<<<node_warp_blocks, 256>>>(conv_b + (size_t)i * HID,
                                                ln_g + (size_t)i * HID,
                                                ln_b + (size_t)i * HID, N,
                                                i == NLAYERS - 1 ? 1 : 0);
    }

    // lin1 (+relu) 3xTF32 split-precision (TBN=128), then lin2
    k_gemm_tf32<128, true><<<tf32_blocks, 256>>>(nullptr, lin1_w, lin1_b,
                                                 N, HID, 2);
    k_lin2<<<node_warp_blocks, 256>>>(lin2_w, lin2_b, out, N);
}